// round 9
// baseline (speedup 1.0000x reference)
#include <cuda_runtime.h>
#include <cuda_bf16.h>
#include <cstdint>

// Problem constants
#define BB 2
#define SSQ 2048
#define DDIM 2048
#define HH 16
#define M1 (BB * SSQ)      // 4096
#define N1 (3 * DDIM)      // 6144
#define FB (BB * HH)       // 32 (b,h) pairs

// ---------------------------------------------------------------------------
// Scratch (__device__ globals: allocation-free rule)
// ---------------------------------------------------------------------------
__device__ __nv_bfloat16 g_qhi[(size_t)FB * SSQ * 128];
__device__ __nv_bfloat16 g_qlo[(size_t)FB * SSQ * 128];
__device__ __nv_bfloat16 g_khi[(size_t)FB * SSQ * 128];
__device__ __nv_bfloat16 g_klo[(size_t)FB * SSQ * 128];
__device__ __nv_bfloat16 g_vhi[(size_t)FB * SSQ * 128];
__device__ __nv_bfloat16 g_vlo[(size_t)FB * SSQ * 128];
// int8 2-digit fixed-point operands
__device__ char g_xa0[(size_t)M1 * DDIM];
__device__ char g_xa1[(size_t)M1 * DDIM];
__device__ char g_w1b0[(size_t)N1 * DDIM];
__device__ char g_w1b1[(size_t)N1 * DDIM];
__device__ char g_w2b0[(size_t)DDIM * DDIM];
__device__ char g_w2b1[(size_t)DDIM * DDIM];
__device__ char g_oa0[(size_t)M1 * DDIM];
__device__ char g_oa1[(size_t)M1 * DDIM];
// flash fp32 output (GEMM2 A operand, pre-quant)
__device__ float g_o[(size_t)M1 * DDIM];
// dynamic per-tensor scales: 0=x, 1=wqkv, 2=wout, 3=o  (float bits as unsigned)
__device__ unsigned g_scales[4];

__device__ __forceinline__ uint32_t smem_u32(const void* p) {
    uint32_t a;
    asm("{ .reg .u64 t; cvta.to.shared.u64 t, %1; cvt.u32.u64 %0, t; }"
        : "=r"(a) : "l"(p));
    return a;
}

#define LDMX4(R, A) \
    asm volatile("ldmatrix.sync.aligned.m8n8.x4.shared.b16 {%0,%1,%2,%3}, [%4];" \
        : "=r"((R)[0]), "=r"((R)[1]), "=r"((R)[2]), "=r"((R)[3]) : "r"(A))
#define LDMX4T(R, A) \
    asm volatile("ldmatrix.sync.aligned.m8n8.x4.trans.shared.b16 {%0,%1,%2,%3}, [%4];" \
        : "=r"((R)[0]), "=r"((R)[1]), "=r"((R)[2]), "=r"((R)[3]) : "r"(A))

#define MMA_BF16(ac, a, b0v, b1v) \
    asm volatile("mma.sync.aligned.m16n8k16.row.col.f32.bf16.bf16.f32 " \
        "{%0,%1,%2,%3},{%4,%5,%6,%7},{%8,%9},{%0,%1,%2,%3};" \
        : "+f"((ac)[0]), "+f"((ac)[1]), "+f"((ac)[2]), "+f"((ac)[3]) \
        : "r"((a)[0]), "r"((a)[1]), "r"((a)[2]), "r"((a)[3]), \
          "r"(b0v), "r"(b1v))

#define MMA_S8(ac, a, b0v, b1v) \
    asm volatile("mma.sync.aligned.m16n8k32.row.col.s32.s8.s8.s32 " \
        "{%0,%1,%2,%3},{%4,%5,%6,%7},{%8,%9},{%0,%1,%2,%3};" \
        : "+r"((ac)[0]), "+r"((ac)[1]), "+r"((ac)[2]), "+r"((ac)[3]) \
        : "r"((a)[0]), "r"((a)[1]), "r"((a)[2]), "r"((a)[3]), \
          "r"(b0v), "r"(b1v))

#define CP_ASYNC16(s, g) \
    asm volatile("cp.async.cg.shared.global [%0], [%1], 16;" :: "r"(s), "l"(g))
#define CP_COMMIT() asm volatile("cp.async.commit_group;" ::: "memory")
#define CP_WAIT1()  asm volatile("cp.async.wait_group 1;" ::: "memory")
#define CP_WAIT0()  asm volatile("cp.async.wait_group 0;" ::: "memory")

// split fp32 pair -> packed bf16x2 (hi) + packed bf16x2 (lo residual)
__device__ __forceinline__ void split_pack(float x, float y,
                                           uint32_t& hi, uint32_t& lo) {
    __nv_bfloat162 h = __floats2bfloat162_rn(x, y);
    hi = *reinterpret_cast<uint32_t*>(&h);
    __nv_bfloat162 l = __floats2bfloat162_rn(x - __low2float(h),
                                             y - __high2float(h));
    lo = *reinterpret_cast<uint32_t*>(&l);
}
__device__ __forceinline__ void split_write(__nv_bfloat16* hi_arr,
                                            __nv_bfloat16* lo_arr,
                                            size_t o, float x, float y) {
    uint32_t hi, lo;
    split_pack(x, y, hi, lo);
    *(uint32_t*)(hi_arr + o) = hi;
    *(uint32_t*)(lo_arr + o) = lo;
}

// ---------------------------------------------------------------------------
// scale reset / maxabs / quantize
// ---------------------------------------------------------------------------
__global__ void reset_scales() {
    if (threadIdx.x < 4) g_scales[threadIdx.x] = 0u;
}

__global__ __launch_bounds__(256) void maxabs_kernel(
    const float* __restrict__ src, int n4, int slot)
{
    float m = 0.0f;
    for (int i = blockIdx.x * blockDim.x + threadIdx.x; i < n4;
         i += gridDim.x * blockDim.x) {
        float4 v = ((const float4*)src)[i];
        m = fmaxf(m, fmaxf(fmaxf(fabsf(v.x), fabsf(v.y)),
                           fmaxf(fabsf(v.z), fabsf(v.w))));
    }
#pragma unroll
    for (int o = 16; o; o >>= 1)
        m = fmaxf(m, __shfl_xor_sync(0xffffffff, m, o));
    if ((threadIdx.x & 31) == 0)
        atomicMax(&g_scales[slot], __float_as_uint(m));
}

__global__ __launch_bounds__(256) void quant_kernel(
    const float* __restrict__ src, char* __restrict__ d0,
    char* __restrict__ d1, int n4, int slot)
{
    int i = blockIdx.x * blockDim.x + threadIdx.x;
    if (i >= n4) return;
    const float S = __uint_as_float(g_scales[slot]) * 1.01f;
    const float kk = 128.0f / S;
    float4 v = ((const float4*)src)[i];
    char q0[4], q1[4];
    float xs[4] = { v.x, v.y, v.z, v.w };
#pragma unroll
    for (int j = 0; j < 4; j++) {
        float t  = xs[j] * kk;
        float a0 = rintf(t);
        float a1 = fminf(fmaxf(rintf((t - a0) * 256.0f), -128.0f), 127.0f);
        q0[j] = (char)(int)a0;
        q1[j] = (char)(int)a1;
    }
    *(char4*)(d0 + (size_t)i * 4) = make_char4(q0[0], q0[1], q0[2], q0[3]);
    *(char4*)(d1 + (size_t)i * 4) = make_char4(q1[0], q1[1], q1[2], q1[3]);
}

// ---------------------------------------------------------------------------
// int8 IMMA GEMM: C[M,N] = A[M,K] * W[N,K]^T, 2-digit fixed point, EXACT
// 4-term product: I0=a0b0, I1=a0b1+a1b0, I2=a1b1.
// CTA 128x128, 512 threads (16 warps, warp tile 64x16), k-chunk 32,
// 3-stage cp.async pipeline. ISTR=48 (16B aligned, conflict-free ldmatrix).
//  MODE 0: dequant -> fp32 store
//  MODE 1: dequant -> RoPE + relayout + bf16 split into g_q/k/v hi/lo
// ---------------------------------------------------------------------------
#define ISTR  48                      // padded row stride (bytes, 32B data)
#define ITILE 6144                    // 128 * 48
#define ISTAGE (4 * ITILE)            // A0,A1,B0,B1 = 24576 B
#define IGEMM_SMEM (3 * ISTAGE)       // 73728 B

template <int MODE>
__global__ __launch_bounds__(512, 1) void imma_gemm_t(
    const char* __restrict__ A0, const char* __restrict__ A1,
    const char* __restrict__ B0, const char* __restrict__ B1,
    float* __restrict__ C, int Ntot, int K, int slotA, int slotB,
    const float* __restrict__ fc, const float* __restrict__ fs)
{
    extern __shared__ char smi[];
    const uint32_t sbase = smem_u32(smi);
    const int t = threadIdx.x;
    const int lane = t & 31, warp = t >> 5;
    const int bm = blockIdx.y << 7;      // 128-row tiles
    const int bn = blockIdx.x << 7;      // 128-col tiles
    const int wm = (warp >> 3) << 6;     // 0 / 64
    const int wn = (warp & 7) << 4;      // 0,16,...,112

    const char* gsrc[4] = { A0, A1, B0, B1 };
    const int gbase[4] = { bm, bm, bn, bn };

    auto load_stage = [&](int kc, int buf) {
        const uint32_t sb = sbase + buf * ISTAGE;
        const int go = kc * 32;
#pragma unroll
        for (int j = 0; j < 2; j++) {
            int flat = j * 512 + t;
            int tile = flat >> 8;
            int rw   = (flat >> 1) & 127;
            int ch   = flat & 1;
            const char* gp = gsrc[tile] + (size_t)(gbase[tile] + rw) * K
                             + go + ch * 16;
            CP_ASYNC16(sb + tile * ITILE + rw * ISTR + ch * 16, gp);
        }
        CP_COMMIT();
    };

    int I0[4][2][4] = {};
    int I1[4][2][4] = {};
    int I2[4][2][4] = {};
    const int NIT = K >> 5;             // K/32

    load_stage(0, 0);
    load_stage(1, 1);

    const int ldrow = lane & 15;
    const int ldc16 = (lane >> 4) << 4;  // byte offset 0 or 16

    int buf = 0;
    for (int it = 0; it < NIT; it++) {
        CP_WAIT1();
        __syncthreads();
        if (it + 2 < NIT) {
            int nb = buf + 2; if (nb >= 3) nb -= 3;
            load_stage(it + 2, nb);
        }

        const uint32_t sb = sbase + buf * ISTAGE;
        uint32_t a0F[4][4], a1F[4][4], b0F[2][2], b1F[2][2];
#pragma unroll
        for (int mt = 0; mt < 4; mt++) {
            uint32_t ra = sb + (wm + mt * 16 + ldrow) * ISTR + ldc16;
            LDMX4(a0F[mt], ra);
            LDMX4(a1F[mt], ra + ITILE);
        }
        {
            uint32_t rb = sb + 2 * ITILE + (wn + ldrow) * ISTR + ldc16;
            uint32_t r[4];
            LDMX4(r, rb);
            b0F[0][0] = r[0]; b0F[0][1] = r[2];
            b0F[1][0] = r[1]; b0F[1][1] = r[3];
            LDMX4(r, rb + ITILE);
            b1F[0][0] = r[0]; b1F[0][1] = r[2];
            b1F[1][0] = r[1]; b1F[1][1] = r[3];
        }
#pragma unroll
        for (int mt = 0; mt < 4; mt++) {
#pragma unroll
            for (int nt = 0; nt < 2; nt++) {
                MMA_S8(I0[mt][nt], a0F[mt], b0F[nt][0], b0F[nt][1]);
                MMA_S8(I1[mt][nt], a0F[mt], b1F[nt][0], b1F[nt][1]);
                MMA_S8(I1[mt][nt], a1F[mt], b0F[nt][0], b0F[nt][1]);
                MMA_S8(I2[mt][nt], a1F[mt], b1F[nt][0], b1F[nt][1]);
            }
        }
        buf++; if (buf == 3) buf = 0;
    }

    // dequant: x*w = Sa*Sb*(I0 + I1/256 + I2/65536)/16384
    const float fsc = (__uint_as_float(g_scales[slotA]) * 1.01f) *
                      (__uint_as_float(g_scales[slotB]) * 1.01f) *
                      (1.0f / 16384.0f);
    const int grp = lane >> 2, qq = (lane & 3) << 1;

#define DEQ(mt, nt, j) \
    (fsc * ((float)I0[mt][nt][j] + 0.00390625f * (float)I1[mt][nt][j] + \
            1.52587890625e-05f * (float)I2[mt][nt][j]))

    if (MODE == 0) {
#pragma unroll
        for (int mt = 0; mt < 4; mt++) {
#pragma unroll
            for (int nt = 0; nt < 2; nt++) {
                float* p = C + (size_t)(bm + wm + mt * 16 + grp) * Ntot
                             + bn + wn + nt * 8 + qq;
                *(float2*)p = make_float2(DEQ(mt, nt, 0), DEQ(mt, nt, 1));
                *(float2*)(p + (size_t)8 * Ntot) =
                    make_float2(DEQ(mt, nt, 2), DEQ(mt, nt, 3));
            }
        }
    } else {
        const int region = bn >> 11;            // 0=q, 1=k, 2=v
        const float scale = 0.08838834764831845f; // 1/sqrt(128)
#pragma unroll
        for (int mt = 0; mt < 4; mt++) {
            const int r0 = bm + wm + mt * 16 + grp;
            const int b  = r0 >> 11;
            const int s0 = r0 & (SSQ - 1);
            const int s1 = s0 + 8;
#pragma unroll
            for (int nt = 0; nt < 2; nt++) {
                float x0 = DEQ(mt, nt, 0), y0 = DEQ(mt, nt, 1);
                float x1 = DEQ(mt, nt, 2), y1 = DEQ(mt, nt, 3);
                const int c  = bn + wn + nt * 8 + qq;
                const int cr = c & (DDIM - 1);
                const int h  = cr >> 7;
                const int ch = cr & 127;
                const int i  = ch >> 1;
                const size_t ob = ((size_t)(b * HH + h) * SSQ);
                const size_t o0 = (ob + s0) * 128 + ch;
                const size_t o1 = (ob + s1) * 128 + ch;
                if (region == 2) {
                    split_write(g_vhi, g_vlo, o0, x0, y0);
                    split_write(g_vhi, g_vlo, o1, x1, y1);
                } else {
                    float c0 = fc[(s0 << 6) + i], sn0 = fs[(s0 << 6) + i];
                    float c1 = fc[(s1 << 6) + i], sn1 = fs[(s1 << 6) + i];
                    float rx0 = x0 * c0 - y0 * sn0, ry0 = x0 * sn0 + y0 * c0;
                    float rx1 = x1 * c1 - y1 * sn1, ry1 = x1 * sn1 + y1 * c1;
                    if (region == 0) {
                        split_write(g_qhi, g_qlo, o0, rx0 * scale, ry0 * scale);
                        split_write(g_qhi, g_qlo, o1, rx1 * scale, ry1 * scale);
                    } else {
                        split_write(g_khi, g_klo, o0, rx0, ry0);
                        split_write(g_khi, g_klo, o1, rx1, ry1);
                    }
                }
            }
        }
    }
#undef DEQ
}

// ---------------------------------------------------------------------------
// Flash attention on mma.sync (bf16 3-term split, fp32 softmax) — unchanged.
// ---------------------------------------------------------------------------
#define FSTR 136
#define FTILE (64 * FSTR)
#define QTILE (128 * FSTR)
#define FLASH_SMEM ((2 * QTILE + 8 * FTILE) * 2)   // 208896 bytes

__global__ __launch_bounds__(256, 1) void flash_mma(
    const __nv_bfloat16* __restrict__ qhi, const __nv_bfloat16* __restrict__ qlo,
    const __nv_bfloat16* __restrict__ khi, const __nv_bfloat16* __restrict__ klo,
    const __nv_bfloat16* __restrict__ vhi, const __nv_bfloat16* __restrict__ vlo,
    float* __restrict__ ofp)
{
    extern __shared__ __nv_bfloat16 fsm[];
    const uint32_t sb = smem_u32(fsm);
    const int t = threadIdx.x;
    const int lane = t & 31, warp = t >> 5;
    const int qt = (int)gridDim.x - 1 - (int)blockIdx.x;
    const int bh = blockIdx.y;
    const int q0 = qt << 7;
    const size_t bhbase = (size_t)bh * SSQ * 128;

    const int ldr = lane & 15;
    const int ldc = (lane >> 4) << 3;
    const int grp = lane >> 2;
    const int qq  = (lane & 3) << 1;

    {
        int r = t >> 1;
        int e0 = (t & 1) << 6;
        const __nv_bfloat16* srcs[2] = {
            qhi + bhbase + (size_t)(q0 + r) * 128 + e0,
            qlo + bhbase + (size_t)(q0 + r) * 128 + e0 };
        uint32_t s0 = sb + (r * FSTR + e0) * 2;
#pragma unroll
        for (int tile = 0; tile < 2; tile++)
#pragma unroll
            for (int c = 0; c < 8; c++)
                CP_ASYNC16(s0 + tile * QTILE * 2 + c * 16, srcs[tile] + c * 8);
        CP_COMMIT();
    }

    auto load_kv = [&](int kt, int buf) {
        int r = t >> 2;
        int e0 = (t & 3) << 5;
        size_t g0 = bhbase + (size_t)(kt * 64 + r) * 128 + e0;
        const __nv_bfloat16* srcs[4] = { khi + g0, klo + g0, vhi + g0, vlo + g0 };
        uint32_t s0 = sb + (2 * QTILE + buf * 4 * FTILE + r * FSTR + e0) * 2;
#pragma unroll
        for (int tile = 0; tile < 4; tile++)
#pragma unroll
            for (int c = 0; c < 4; c++)
                CP_ASYNC16(s0 + tile * FTILE * 2 + c * 16, srcs[tile] + c * 8);
        CP_COMMIT();
    };

    CP_WAIT0();
    __syncthreads();
    uint32_t qh[8][4], ql[8][4];
    const int wrow = warp << 4;
#pragma unroll
    for (int d = 0; d < 8; d++) {
        uint32_t a = sb + ((wrow + ldr) * FSTR + d * 16 + ldc) * 2;
        LDMX4(qh[d], a);
        LDMX4(ql[d], a + QTILE * 2);
    }

    const int ktmax = 2 * qt + 1;
    load_kv(0, 0);
    load_kv(1, 1);

    float Of[16][4] = {};
    float m0 = -1e30f, m1 = -1e30f, l0 = 0.f, l1 = 0.f;

    for (int kt = 0; kt <= ktmax; kt++) {
        if (kt == ktmax) { CP_WAIT0(); } else { CP_WAIT1(); }
        __syncthreads();

        const uint32_t kvb = sb + (2 * QTILE + (kt & 1) * 4 * FTILE) * 2;

        float Sf[8][4] = {};
#pragma unroll
        for (int d = 0; d < 8; d++) {
#pragma unroll
            for (int n4 = 0; n4 < 4; n4++) {
                uint32_t addr = kvb + ((n4 * 16 + ldr) * FSTR + d * 16 + ldc) * 2;
                uint32_t kb0[4], kb1[4];
                LDMX4(kb0, addr);
                LDMX4(kb1, addr + FTILE * 2);
                MMA_BF16(Sf[2 * n4],     qh[d], kb0[0], kb0[2]);
                MMA_BF16(Sf[2 * n4 + 1], qh[d], kb0[1], kb0[3]);
                MMA_BF16(Sf[2 * n4],     qh[d], kb1[0], kb1[2]);
                MMA_BF16(Sf[2 * n4 + 1], qh[d], kb1[1], kb1[3]);
                MMA_BF16(Sf[2 * n4],     ql[d], kb0[0], kb0[2]);
                MMA_BF16(Sf[2 * n4 + 1], ql[d], kb0[1], kb0[3]);
            }
        }

        const int r0 = q0 + wrow + grp;
        if (kt >= 2 * qt) {
#pragma unroll
            for (int nb = 0; nb < 8; nb++) {
#pragma unroll
                for (int j = 0; j < 2; j++) {
                    int key = kt * 64 + nb * 8 + qq + j;
                    if (key > r0)     Sf[nb][j]     = -1e30f;
                    if (key > r0 + 8) Sf[nb][2 + j] = -1e30f;
                }
            }
        }

        float mx0 = -1e30f, mx1 = -1e30f;
#pragma unroll
        for (int nb = 0; nb < 8; nb++) {
            mx0 = fmaxf(mx0, fmaxf(Sf[nb][0], Sf[nb][1]));
            mx1 = fmaxf(mx1, fmaxf(Sf[nb][2], Sf[nb][3]));
        }
        mx0 = fmaxf(mx0, __shfl_xor_sync(0xffffffff, mx0, 1));
        mx0 = fmaxf(mx0, __shfl_xor_sync(0xffffffff, mx0, 2));
        mx1 = fmaxf(mx1, __shfl_xor_sync(0xffffffff, mx1, 1));
        mx1 = fmaxf(mx1, __shfl_xor_sync(0xffffffff, mx1, 2));
        float mn0 = fmaxf(m0, mx0), mn1 = fmaxf(m1, mx1);
        float a0 = __expf(m0 - mn0), a1 = __expf(m1 - mn1);
        float s0 = 0.f, s1 = 0.f;
#pragma unroll
        for (int nb = 0; nb < 8; nb++) {
            Sf[nb][0] = __expf(Sf[nb][0] - mn0); s0 += Sf[nb][0];
            Sf[nb][1] = __expf(Sf[nb][1] - mn0); s0 += Sf[nb][1];
            Sf[nb][2] = __expf(Sf[nb][2] - mn1); s1 += Sf[nb][2];
            Sf[nb][3] = __expf(Sf[nb][3] - mn1); s1 += Sf[nb][3];
        }
        s0 += __shfl_xor_sync(0xffffffff, s0, 1);
        s0 += __shfl_xor_sync(0xffffffff, s0, 2);
        s1 += __shfl_xor_sync(0xffffffff, s1, 1);
        s1 += __shfl_xor_sync(0xffffffff, s1, 2);
        l0 = l0 * a0 + s0;  l1 = l1 * a1 + s1;
        m0 = mn0;           m1 = mn1;
#pragma unroll
        for (int nb = 0; nb < 16; nb++) {
            Of[nb][0] *= a0; Of[nb][1] *= a0;
            Of[nb][2] *= a1; Of[nb][3] *= a1;
        }

        const uint32_t vb = kvb + 2 * FTILE * 2;
#pragma unroll
        for (int j = 0; j < 4; j++) {
            uint32_t ph[4], pl[4];
            split_pack(Sf[2 * j][0],     Sf[2 * j][1],     ph[0], pl[0]);
            split_pack(Sf[2 * j][2],     Sf[2 * j][3],     ph[1], pl[1]);
            split_pack(Sf[2 * j + 1][0], Sf[2 * j + 1][1], ph[2], pl[2]);
            split_pack(Sf[2 * j + 1][2], Sf[2 * j + 1][3], ph[3], pl[3]);
#pragma unroll
            for (int nb2 = 0; nb2 < 8; nb2++) {
                uint32_t addr = vb + ((j * 16 + ldr) * FSTR + nb2 * 16 + ldc) * 2;
                uint32_t vh[4], vl[4];
                LDMX4T(vh, addr);
                LDMX4T(vl, addr + FTILE * 2);
                MMA_BF16(Of[2 * nb2],     ph, vh[0], vh[1]);
                MMA_BF16(Of[2 * nb2 + 1], ph, vh[2], vh[3]);
                MMA_BF16(Of[2 * nb2],     ph, vl[0], vl[1]);
                MMA_BF16(Of[2 * nb2 + 1], ph, vl[2], vl[3]);
                MMA_BF16(Of[2 * nb2],     pl, vh[0], vh[1]);
                MMA_BF16(Of[2 * nb2 + 1], pl, vh[2], vh[3]);
            }
        }

        __syncthreads();
        if (kt + 2 <= ktmax) load_kv(kt + 2, kt & 1);
    }

    const int b = bh >> 4, h = bh & 15;
    const float inv0 = 1.0f / l0, inv1 = 1.0f / l1;
    const size_t row0 = (size_t)(b * SSQ + q0 + wrow + grp) * DDIM + (h << 7);
    const size_t row1 = row0 + (size_t)8 * DDIM;
#pragma unroll
    for (int nb = 0; nb < 16; nb++) {
        *(float2*)(ofp + row0 + nb * 8 + qq) =
            make_float2(Of[nb][0] * inv0, Of[nb][1] * inv0);
        *(float2*)(ofp + row1 + nb * 8 + qq) =
            make_float2(Of[nb][2] * inv1, Of[nb][3] * inv1);
    }
}

// ---------------------------------------------------------------------------
// Launch
// ---------------------------------------------------------------------------
extern "C" void kernel_launch(void* const* d_in, const int* in_sizes, int n_in,
                              void* d_out, int out_size)
{
    const float* x     = (const float*)d_in[0];
    const float* wqkv  = (const float*)d_in[1];
    const float* wout  = (const float*)d_in[2];
    const float* fcos  = (const float*)d_in[3];
    const float* fsin  = (const float*)d_in[4];
    float* out = (float*)d_out;

    __nv_bfloat16 *qh, *ql, *kh, *kl, *vh, *vl;
    char *xa0, *xa1, *w1b0, *w1b1, *w2b0, *w2b1, *oa0, *oa1;
    float* o_p;
    cudaGetSymbolAddress((void**)&qh, g_qhi);
    cudaGetSymbolAddress((void**)&ql, g_qlo);
    cudaGetSymbolAddress((void**)&kh, g_khi);
    cudaGetSymbolAddress((void**)&kl, g_klo);
    cudaGetSymbolAddress((void**)&vh, g_vhi);
    cudaGetSymbolAddress((void**)&vl, g_vlo);
    cudaGetSymbolAddress((void**)&xa0, g_xa0);
    cudaGetSymbolAddress((void**)&xa1, g_xa1);
    cudaGetSymbolAddress((void**)&w1b0, g_w1b0);
    cudaGetSymbolAddress((void**)&w1b1, g_w1b1);
    cudaGetSymbolAddress((void**)&w2b0, g_w2b0);
    cudaGetSymbolAddress((void**)&w2b1, g_w2b1);
    cudaGetSymbolAddress((void**)&oa0, g_oa0);
    cudaGetSymbolAddress((void**)&oa1, g_oa1);
    cudaGetSymbolAddress((void**)&o_p, g_o);

    cudaFuncSetAttribute(imma_gemm_t<0>,
                         cudaFuncAttributeMaxDynamicSharedMemorySize, IGEMM_SMEM);
    cudaFuncSetAttribute(imma_gemm_t<1>,
                         cudaFuncAttributeMaxDynamicSharedMemorySize, IGEMM_SMEM);
    cudaFuncSetAttribute(flash_mma,
                         cudaFuncAttributeMaxDynamicSharedMemorySize, FLASH_SMEM);

    const int nx  = M1 * DDIM / 4;
    const int nw1 = N1 * DDIM / 4;
    const int nw2 = DDIM * DDIM / 4;

    // scales + quantization
    reset_scales<<<1, 32>>>();
    maxabs_kernel<<<1024, 256>>>(x, nx, 0);
    maxabs_kernel<<<1024, 256>>>(wqkv, nw1, 1);
    maxabs_kernel<<<1024, 256>>>(wout, nw2, 2);
    quant_kernel<<<(nx + 255) / 256, 256>>>(x, xa0, xa1, nx, 0);
    quant_kernel<<<(nw1 + 255) / 256, 256>>>(wqkv, w1b0, w1b1, nw1, 1);
    quant_kernel<<<(nw2 + 255) / 256, 256>>>(wout, w2b0, w2b1, nw2, 2);

    // 1) QKV projection (int8 IMMA) with fused dequant+RoPE+split epilogue
    imma_gemm_t<1><<<dim3(N1 / 128, M1 / 128), 512, IGEMM_SMEM>>>(
        xa0, xa1, w1b0, w1b1, nullptr, N1, DDIM, 0, 1, fcos, fsin);

    // 2) Flash attention (bf16 mma.sync) -> fp32 g_o
    flash_mma<<<dim3(SSQ / 128, FB), 256, FLASH_SMEM>>>(
        qh, ql, kh, kl, vh, vl, o_p);

    // 3) quantize attention output, then output projection (int8 IMMA)
    maxabs_kernel<<<1024, 256>>>(o_p, nx, 3);
    quant_kernel<<<(nx + 255) / 256, 256>>>(o_p, oa0, oa1, nx, 3);
    imma_gemm_t<0><<<dim3(DDIM / 128, M1 / 128), 512, IGEMM_SMEM>>>(
        oa0, oa1, w2b0, w2b1, out, DDIM, DDIM, 3, 2, nullptr, nullptr);
}

// round 10
// speedup vs baseline: 1.0170x; 1.0170x over previous
#include <cuda_runtime.h>
#include <cuda_bf16.h>
#include <cstdint>

// Problem constants
#define BB 2
#define SSQ 2048
#define DDIM 2048
#define HH 16
#define M1 (BB * SSQ)      // 4096
#define N1 (3 * DDIM)      // 6144
#define FB (BB * HH)       // 32 (b,h) pairs

// ---------------------------------------------------------------------------
// Scratch (__device__ globals: allocation-free rule)
// ---------------------------------------------------------------------------
__device__ __nv_bfloat16 g_qhi[(size_t)FB * SSQ * 128];
__device__ __nv_bfloat16 g_qlo[(size_t)FB * SSQ * 128];
__device__ __nv_bfloat16 g_khi[(size_t)FB * SSQ * 128];
__device__ __nv_bfloat16 g_klo[(size_t)FB * SSQ * 128];
__device__ __nv_bfloat16 g_vhi[(size_t)FB * SSQ * 128];
__device__ __nv_bfloat16 g_vlo[(size_t)FB * SSQ * 128];
// int8 2-digit fixed-point operands
__device__ char g_xa0[(size_t)M1 * DDIM];
__device__ char g_xa1[(size_t)M1 * DDIM];
__device__ char g_w1b0[(size_t)N1 * DDIM];
__device__ char g_w1b1[(size_t)N1 * DDIM];
__device__ char g_w2b0[(size_t)DDIM * DDIM];
__device__ char g_w2b1[(size_t)DDIM * DDIM];
__device__ char g_oa0[(size_t)M1 * DDIM];
__device__ char g_oa1[(size_t)M1 * DDIM];
// flash fp32 output (GEMM2 A operand, pre-quant)
__device__ float g_o[(size_t)M1 * DDIM];
// dynamic per-tensor scales: 0=x, 1=wqkv, 2=wout, 3=o  (float bits as unsigned)
__device__ unsigned g_scales[4];

__device__ __forceinline__ uint32_t smem_u32(const void* p) {
    uint32_t a;
    asm("{ .reg .u64 t; cvta.to.shared.u64 t, %1; cvt.u32.u64 %0, t; }"
        : "=r"(a) : "l"(p));
    return a;
}

#define LDMX4(R, A) \
    asm volatile("ldmatrix.sync.aligned.m8n8.x4.shared.b16 {%0,%1,%2,%3}, [%4];" \
        : "=r"((R)[0]), "=r"((R)[1]), "=r"((R)[2]), "=r"((R)[3]) : "r"(A))
#define LDMX4T(R, A) \
    asm volatile("ldmatrix.sync.aligned.m8n8.x4.trans.shared.b16 {%0,%1,%2,%3}, [%4];" \
        : "=r"((R)[0]), "=r"((R)[1]), "=r"((R)[2]), "=r"((R)[3]) : "r"(A))

#define MMA_BF16(ac, a, b0v, b1v) \
    asm volatile("mma.sync.aligned.m16n8k16.row.col.f32.bf16.bf16.f32 " \
        "{%0,%1,%2,%3},{%4,%5,%6,%7},{%8,%9},{%0,%1,%2,%3};" \
        : "+f"((ac)[0]), "+f"((ac)[1]), "+f"((ac)[2]), "+f"((ac)[3]) \
        : "r"((a)[0]), "r"((a)[1]), "r"((a)[2]), "r"((a)[3]), \
          "r"(b0v), "r"(b1v))

#define MMA_S8(ac, a, b0v, b1v) \
    asm volatile("mma.sync.aligned.m16n8k32.row.col.s32.s8.s8.s32 " \
        "{%0,%1,%2,%3},{%4,%5,%6,%7},{%8,%9},{%0,%1,%2,%3};" \
        : "+r"((ac)[0]), "+r"((ac)[1]), "+r"((ac)[2]), "+r"((ac)[3]) \
        : "r"((a)[0]), "r"((a)[1]), "r"((a)[2]), "r"((a)[3]), \
          "r"(b0v), "r"(b1v))

#define CP_ASYNC16(s, g) \
    asm volatile("cp.async.cg.shared.global [%0], [%1], 16;" :: "r"(s), "l"(g))
#define CP_COMMIT() asm volatile("cp.async.commit_group;" ::: "memory")
#define CP_WAIT1()  asm volatile("cp.async.wait_group 1;" ::: "memory")
#define CP_WAIT0()  asm volatile("cp.async.wait_group 0;" ::: "memory")

// split fp32 pair -> packed bf16x2 (hi) + packed bf16x2 (lo residual)
__device__ __forceinline__ void split_pack(float x, float y,
                                           uint32_t& hi, uint32_t& lo) {
    __nv_bfloat162 h = __floats2bfloat162_rn(x, y);
    hi = *reinterpret_cast<uint32_t*>(&h);
    __nv_bfloat162 l = __floats2bfloat162_rn(x - __low2float(h),
                                             y - __high2float(h));
    lo = *reinterpret_cast<uint32_t*>(&l);
}
__device__ __forceinline__ void split_write(__nv_bfloat16* hi_arr,
                                            __nv_bfloat16* lo_arr,
                                            size_t o, float x, float y) {
    uint32_t hi, lo;
    split_pack(x, y, hi, lo);
    *(uint32_t*)(hi_arr + o) = hi;
    *(uint32_t*)(lo_arr + o) = lo;
}

// ---------------------------------------------------------------------------
// scale reset / maxabs / quantize
// ---------------------------------------------------------------------------
__global__ void reset_scales() {
    if (threadIdx.x < 4) g_scales[threadIdx.x] = 0u;
}

__global__ __launch_bounds__(256) void maxabs_kernel(
    const float* __restrict__ src, int n4, int slot)
{
    float m = 0.0f;
    for (int i = blockIdx.x * blockDim.x + threadIdx.x; i < n4;
         i += gridDim.x * blockDim.x) {
        float4 v = ((const float4*)src)[i];
        m = fmaxf(m, fmaxf(fmaxf(fabsf(v.x), fabsf(v.y)),
                           fmaxf(fabsf(v.z), fabsf(v.w))));
    }
#pragma unroll
    for (int o = 16; o; o >>= 1)
        m = fmaxf(m, __shfl_xor_sync(0xffffffff, m, o));
    if ((threadIdx.x & 31) == 0)
        atomicMax(&g_scales[slot], __float_as_uint(m));
}

__global__ __launch_bounds__(256) void quant_kernel(
    const float* __restrict__ src, char* __restrict__ d0,
    char* __restrict__ d1, int n4, int slot)
{
    int i = blockIdx.x * blockDim.x + threadIdx.x;
    if (i >= n4) return;
    const float S = __uint_as_float(g_scales[slot]) * 1.01f;
    const float kk = 128.0f / S;
    float4 v = ((const float4*)src)[i];
    char q0[4], q1[4];
    float xs[4] = { v.x, v.y, v.z, v.w };
#pragma unroll
    for (int j = 0; j < 4; j++) {
        float t  = xs[j] * kk;
        float a0 = rintf(t);
        float a1 = fminf(fmaxf(rintf((t - a0) * 256.0f), -128.0f), 127.0f);
        q0[j] = (char)(int)a0;
        q1[j] = (char)(int)a1;
    }
    *(char4*)(d0 + (size_t)i * 4) = make_char4(q0[0], q0[1], q0[2], q0[3]);
    *(char4*)(d1 + (size_t)i * 4) = make_char4(q1[0], q1[1], q1[2], q1[3]);
}

// ---------------------------------------------------------------------------
// int8 IMMA GEMM: C[M,N] = A[M,K] * W[N,K]^T, 2-digit fixed point, EXACT
// 4-term product: I0=a0b0, I1=a0b1+a1b0, I2=a1b1.
// CTA 128x64, 256 threads (8 warps, warp tile 64x16, 2x4 layout), k-chunk 32,
// 3-stage cp.async pipeline. ISTR=48 (16B aligned, conflict-free ldmatrix).
// 256 threads -> 255-reg cap -> NO accumulator spills (the R9 failure).
//  MODE 0: dequant -> fp32 store
//  MODE 1: dequant -> RoPE + relayout + bf16 split into g_q/k/v hi/lo
// ---------------------------------------------------------------------------
#define ISTR   48                     // padded row stride (bytes, 32B data)
#define IA_T   6144                   // A digit tile: 128*48
#define IB_T   3072                   // B digit tile: 64*48
#define IB_OFF (2 * IA_T)             // 12288
#define ISTAGE (2 * IA_T + 2 * IB_T)  // 18432 B
#define IGEMM_SMEM (3 * ISTAGE)       // 55296 B

template <int MODE>
__global__ __launch_bounds__(256) void imma_gemm_t(
    const char* __restrict__ A0, const char* __restrict__ A1,
    const char* __restrict__ B0, const char* __restrict__ B1,
    float* __restrict__ C, int Ntot, int K, int slotA, int slotB,
    const float* __restrict__ fc, const float* __restrict__ fs)
{
    extern __shared__ char smi[];
    const uint32_t sbase = smem_u32(smi);
    const int t = threadIdx.x;
    const int lane = t & 31, warp = t >> 5;
    const int bm = blockIdx.y << 7;      // 128-row tiles
    const int bn = blockIdx.x << 6;      // 64-col tiles
    const int wm = (warp >> 2) << 6;     // 0 / 64
    const int wn = (warp & 3) << 4;      // 0,16,32,48

    // loader mapping (3 cp.async per thread)
    const int rA  = t >> 1;              // 0..127
    const int cA  = t & 1;
    const int hB  = t >> 7;              // 0 -> B0, 1 -> B1
    const int rB  = (t & 127) >> 1;      // 0..63
    const int cB  = t & 1;

    const char* gA0 = A0 + (size_t)(bm + rA) * K + cA * 16;
    const char* gA1 = A1 + (size_t)(bm + rA) * K + cA * 16;
    const char* gB  = (hB ? B1 : B0) + (size_t)(bn + rB) * K + cB * 16;

    const uint32_t sA0 = sbase + rA * ISTR + cA * 16;
    const uint32_t sA1 = sA0 + IA_T;
    const uint32_t sB  = sbase + IB_OFF + hB * IB_T + rB * ISTR + cB * 16;

    auto load_stage = [&](int kc, int buf) {
        const uint32_t so = buf * ISTAGE;
        const int go = kc * 32;
        CP_ASYNC16(sA0 + so, gA0 + go);
        CP_ASYNC16(sA1 + so, gA1 + go);
        CP_ASYNC16(sB  + so, gB  + go);
        CP_COMMIT();
    };

    int I0[4][2][4] = {};
    int I1[4][2][4] = {};
    int I2[4][2][4] = {};
    const int NIT = K >> 5;             // K/32

    load_stage(0, 0);
    load_stage(1, 1);

    const int ldrow = lane & 15;
    const int ldc16 = (lane >> 4) << 4;  // byte offset 0 or 16

    int buf = 0;
    for (int it = 0; it < NIT; it++) {
        CP_WAIT1();
        __syncthreads();
        if (it + 2 < NIT) {
            int nb = buf + 2; if (nb >= 3) nb -= 3;
            load_stage(it + 2, nb);
        }

        const uint32_t sb = sbase + buf * ISTAGE;
        uint32_t a0F[4][4], a1F[4][4], b0F[2][2], b1F[2][2];
#pragma unroll
        for (int mt = 0; mt < 4; mt++) {
            uint32_t ra = sb + (wm + mt * 16 + ldrow) * ISTR + ldc16;
            LDMX4(a0F[mt], ra);
            LDMX4(a1F[mt], ra + IA_T);
        }
        {
            uint32_t rb = sb + IB_OFF + (wn + ldrow) * ISTR + ldc16;
            uint32_t r[4];
            LDMX4(r, rb);
            b0F[0][0] = r[0]; b0F[0][1] = r[2];
            b0F[1][0] = r[1]; b0F[1][1] = r[3];
            LDMX4(r, rb + IB_T);
            b1F[0][0] = r[0]; b1F[0][1] = r[2];
            b1F[1][0] = r[1]; b1F[1][1] = r[3];
        }
#pragma unroll
        for (int mt = 0; mt < 4; mt++) {
#pragma unroll
            for (int nt = 0; nt < 2; nt++) {
                MMA_S8(I0[mt][nt], a0F[mt], b0F[nt][0], b0F[nt][1]);
                MMA_S8(I1[mt][nt], a0F[mt], b1F[nt][0], b1F[nt][1]);
                MMA_S8(I1[mt][nt], a1F[mt], b0F[nt][0], b0F[nt][1]);
                MMA_S8(I2[mt][nt], a1F[mt], b1F[nt][0], b1F[nt][1]);
            }
        }
        buf++; if (buf == 3) buf = 0;
    }

    // dequant: x*w = Sa*Sb*(I0 + I1/256 + I2/65536)/16384
    const float fsc = (__uint_as_float(g_scales[slotA]) * 1.01f) *
                      (__uint_as_float(g_scales[slotB]) * 1.01f) *
                      (1.0f / 16384.0f);
    const int grp = lane >> 2, qq = (lane & 3) << 1;

#define DEQ(mt, nt, j) \
    (fsc * ((float)I0[mt][nt][j] + 0.00390625f * (float)I1[mt][nt][j] + \
            1.52587890625e-05f * (float)I2[mt][nt][j]))

    if (MODE == 0) {
#pragma unroll
        for (int mt = 0; mt < 4; mt++) {
#pragma unroll
            for (int nt = 0; nt < 2; nt++) {
                float* p = C + (size_t)(bm + wm + mt * 16 + grp) * Ntot
                             + bn + wn + nt * 8 + qq;
                *(float2*)p = make_float2(DEQ(mt, nt, 0), DEQ(mt, nt, 1));
                *(float2*)(p + (size_t)8 * Ntot) =
                    make_float2(DEQ(mt, nt, 2), DEQ(mt, nt, 3));
            }
        }
    } else {
        const int region = bn >> 11;            // 0=q, 1=k, 2=v
        const float scale = 0.08838834764831845f; // 1/sqrt(128)
#pragma unroll
        for (int mt = 0; mt < 4; mt++) {
            const int r0 = bm + wm + mt * 16 + grp;
            const int b  = r0 >> 11;
            const int s0 = r0 & (SSQ - 1);
            const int s1 = s0 + 8;
#pragma unroll
            for (int nt = 0; nt < 2; nt++) {
                float x0 = DEQ(mt, nt, 0), y0 = DEQ(mt, nt, 1);
                float x1 = DEQ(mt, nt, 2), y1 = DEQ(mt, nt, 3);
                const int c  = bn + wn + nt * 8 + qq;
                const int cr = c & (DDIM - 1);
                const int h  = cr >> 7;
                const int ch = cr & 127;
                const int i  = ch >> 1;
                const size_t ob = ((size_t)(b * HH + h) * SSQ);
                const size_t o0 = (ob + s0) * 128 + ch;
                const size_t o1 = (ob + s1) * 128 + ch;
                if (region == 2) {
                    split_write(g_vhi, g_vlo, o0, x0, y0);
                    split_write(g_vhi, g_vlo, o1, x1, y1);
                } else {
                    float c0 = fc[(s0 << 6) + i], sn0 = fs[(s0 << 6) + i];
                    float c1 = fc[(s1 << 6) + i], sn1 = fs[(s1 << 6) + i];
                    float rx0 = x0 * c0 - y0 * sn0, ry0 = x0 * sn0 + y0 * c0;
                    float rx1 = x1 * c1 - y1 * sn1, ry1 = x1 * sn1 + y1 * c1;
                    if (region == 0) {
                        split_write(g_qhi, g_qlo, o0, rx0 * scale, ry0 * scale);
                        split_write(g_qhi, g_qlo, o1, rx1 * scale, ry1 * scale);
                    } else {
                        split_write(g_khi, g_klo, o0, rx0, ry0);
                        split_write(g_khi, g_klo, o1, rx1, ry1);
                    }
                }
            }
        }
    }
#undef DEQ
}

// ---------------------------------------------------------------------------
// Flash attention on mma.sync (bf16 3-term split, fp32 softmax) — unchanged.
// ---------------------------------------------------------------------------
#define FSTR 136
#define FTILE (64 * FSTR)
#define QTILE (128 * FSTR)
#define FLASH_SMEM ((2 * QTILE + 8 * FTILE) * 2)   // 208896 bytes

__global__ __launch_bounds__(256, 1) void flash_mma(
    const __nv_bfloat16* __restrict__ qhi, const __nv_bfloat16* __restrict__ qlo,
    const __nv_bfloat16* __restrict__ khi, const __nv_bfloat16* __restrict__ klo,
    const __nv_bfloat16* __restrict__ vhi, const __nv_bfloat16* __restrict__ vlo,
    float* __restrict__ ofp)
{
    extern __shared__ __nv_bfloat16 fsm[];
    const uint32_t sb = smem_u32(fsm);
    const int t = threadIdx.x;
    const int lane = t & 31, warp = t >> 5;
    const int qt = (int)gridDim.x - 1 - (int)blockIdx.x;
    const int bh = blockIdx.y;
    const int q0 = qt << 7;
    const size_t bhbase = (size_t)bh * SSQ * 128;

    const int ldr = lane & 15;
    const int ldc = (lane >> 4) << 3;
    const int grp = lane >> 2;
    const int qq  = (lane & 3) << 1;

    {
        int r = t >> 1;
        int e0 = (t & 1) << 6;
        const __nv_bfloat16* srcs[2] = {
            qhi + bhbase + (size_t)(q0 + r) * 128 + e0,
            qlo + bhbase + (size_t)(q0 + r) * 128 + e0 };
        uint32_t s0 = sb + (r * FSTR + e0) * 2;
#pragma unroll
        for (int tile = 0; tile < 2; tile++)
#pragma unroll
            for (int c = 0; c < 8; c++)
                CP_ASYNC16(s0 + tile * QTILE * 2 + c * 16, srcs[tile] + c * 8);
        CP_COMMIT();
    }

    auto load_kv = [&](int kt, int buf) {
        int r = t >> 2;
        int e0 = (t & 3) << 5;
        size_t g0 = bhbase + (size_t)(kt * 64 + r) * 128 + e0;
        const __nv_bfloat16* srcs[4] = { khi + g0, klo + g0, vhi + g0, vlo + g0 };
        uint32_t s0 = sb + (2 * QTILE + buf * 4 * FTILE + r * FSTR + e0) * 2;
#pragma unroll
        for (int tile = 0; tile < 4; tile++)
#pragma unroll
            for (int c = 0; c < 4; c++)
                CP_ASYNC16(s0 + tile * FTILE * 2 + c * 16, srcs[tile] + c * 8);
        CP_COMMIT();
    };

    CP_WAIT0();
    __syncthreads();
    uint32_t qh[8][4], ql[8][4];
    const int wrow = warp << 4;
#pragma unroll
    for (int d = 0; d < 8; d++) {
        uint32_t a = sb + ((wrow + ldr) * FSTR + d * 16 + ldc) * 2;
        LDMX4(qh[d], a);
        LDMX4(ql[d], a + QTILE * 2);
    }

    const int ktmax = 2 * qt + 1;
    load_kv(0, 0);
    load_kv(1, 1);

    float Of[16][4] = {};
    float m0 = -1e30f, m1 = -1e30f, l0 = 0.f, l1 = 0.f;

    for (int kt = 0; kt <= ktmax; kt++) {
        if (kt == ktmax) { CP_WAIT0(); } else { CP_WAIT1(); }
        __syncthreads();

        const uint32_t kvb = sb + (2 * QTILE + (kt & 1) * 4 * FTILE) * 2;

        float Sf[8][4] = {};
#pragma unroll
        for (int d = 0; d < 8; d++) {
#pragma unroll
            for (int n4 = 0; n4 < 4; n4++) {
                uint32_t addr = kvb + ((n4 * 16 + ldr) * FSTR + d * 16 + ldc) * 2;
                uint32_t kb0[4], kb1[4];
                LDMX4(kb0, addr);
                LDMX4(kb1, addr + FTILE * 2);
                MMA_BF16(Sf[2 * n4],     qh[d], kb0[0], kb0[2]);
                MMA_BF16(Sf[2 * n4 + 1], qh[d], kb0[1], kb0[3]);
                MMA_BF16(Sf[2 * n4],     qh[d], kb1[0], kb1[2]);
                MMA_BF16(Sf[2 * n4 + 1], qh[d], kb1[1], kb1[3]);
                MMA_BF16(Sf[2 * n4],     ql[d], kb0[0], kb0[2]);
                MMA_BF16(Sf[2 * n4 + 1], ql[d], kb0[1], kb0[3]);
            }
        }

        const int r0 = q0 + wrow + grp;
        if (kt >= 2 * qt) {
#pragma unroll
            for (int nb = 0; nb < 8; nb++) {
#pragma unroll
                for (int j = 0; j < 2; j++) {
                    int key = kt * 64 + nb * 8 + qq + j;
                    if (key > r0)     Sf[nb][j]     = -1e30f;
                    if (key > r0 + 8) Sf[nb][2 + j] = -1e30f;
                }
            }
        }

        float mx0 = -1e30f, mx1 = -1e30f;
#pragma unroll
        for (int nb = 0; nb < 8; nb++) {
            mx0 = fmaxf(mx0, fmaxf(Sf[nb][0], Sf[nb][1]));
            mx1 = fmaxf(mx1, fmaxf(Sf[nb][2], Sf[nb][3]));
        }
        mx0 = fmaxf(mx0, __shfl_xor_sync(0xffffffff, mx0, 1));
        mx0 = fmaxf(mx0, __shfl_xor_sync(0xffffffff, mx0, 2));
        mx1 = fmaxf(mx1, __shfl_xor_sync(0xffffffff, mx1, 1));
        mx1 = fmaxf(mx1, __shfl_xor_sync(0xffffffff, mx1, 2));
        float mn0 = fmaxf(m0, mx0), mn1 = fmaxf(m1, mx1);
        float a0 = __expf(m0 - mn0), a1 = __expf(m1 - mn1);
        float s0 = 0.f, s1 = 0.f;
#pragma unroll
        for (int nb = 0; nb < 8; nb++) {
            Sf[nb][0] = __expf(Sf[nb][0] - mn0); s0 += Sf[nb][0];
            Sf[nb][1] = __expf(Sf[nb][1] - mn0); s0 += Sf[nb][1];
            Sf[nb][2] = __expf(Sf[nb][2] - mn1); s1 += Sf[nb][2];
            Sf[nb][3] = __expf(Sf[nb][3] - mn1); s1 += Sf[nb][3];
        }
        s0 += __shfl_xor_sync(0xffffffff, s0, 1);
        s0 += __shfl_xor_sync(0xffffffff, s0, 2);
        s1 += __shfl_xor_sync(0xffffffff, s1, 1);
        s1 += __shfl_xor_sync(0xffffffff, s1, 2);
        l0 = l0 * a0 + s0;  l1 = l1 * a1 + s1;
        m0 = mn0;           m1 = mn1;
#pragma unroll
        for (int nb = 0; nb < 16; nb++) {
            Of[nb][0] *= a0; Of[nb][1] *= a0;
            Of[nb][2] *= a1; Of[nb][3] *= a1;
        }

        const uint32_t vb = kvb + 2 * FTILE * 2;
#pragma unroll
        for (int j = 0; j < 4; j++) {
            uint32_t ph[4], pl[4];
            split_pack(Sf[2 * j][0],     Sf[2 * j][1],     ph[0], pl[0]);
            split_pack(Sf[2 * j][2],     Sf[2 * j][3],     ph[1], pl[1]);
            split_pack(Sf[2 * j + 1][0], Sf[2 * j + 1][1], ph[2], pl[2]);
            split_pack(Sf[2 * j + 1][2], Sf[2 * j + 1][3], ph[3], pl[3]);
#pragma unroll
            for (int nb2 = 0; nb2 < 8; nb2++) {
                uint32_t addr = vb + ((j * 16 + ldr) * FSTR + nb2 * 16 + ldc) * 2;
                uint32_t vh[4], vl[4];
                LDMX4T(vh, addr);
                LDMX4T(vl, addr + FTILE * 2);
                MMA_BF16(Of[2 * nb2],     ph, vh[0], vh[1]);
                MMA_BF16(Of[2 * nb2 + 1], ph, vh[2], vh[3]);
                MMA_BF16(Of[2 * nb2],     ph, vl[0], vl[1]);
                MMA_BF16(Of[2 * nb2 + 1], ph, vl[2], vl[3]);
                MMA_BF16(Of[2 * nb2],     pl, vh[0], vh[1]);
                MMA_BF16(Of[2 * nb2 + 1], pl, vh[2], vh[3]);
            }
        }

        __syncthreads();
        if (kt + 2 <= ktmax) load_kv(kt + 2, kt & 1);
    }

    const int b = bh >> 4, h = bh & 15;
    const float inv0 = 1.0f / l0, inv1 = 1.0f / l1;
    const size_t row0 = (size_t)(b * SSQ + q0 + wrow + grp) * DDIM + (h << 7);
    const size_t row1 = row0 + (size_t)8 * DDIM;
#pragma unroll
    for (int nb = 0; nb < 16; nb++) {
        *(float2*)(ofp + row0 + nb * 8 + qq) =
            make_float2(Of[nb][0] * inv0, Of[nb][1] * inv0);
        *(float2*)(ofp + row1 + nb * 8 + qq) =
            make_float2(Of[nb][2] * inv1, Of[nb][3] * inv1);
    }
}

// ---------------------------------------------------------------------------
// Launch
// ---------------------------------------------------------------------------
extern "C" void kernel_launch(void* const* d_in, const int* in_sizes, int n_in,
                              void* d_out, int out_size)
{
    const float* x     = (const float*)d_in[0];
    const float* wqkv  = (const float*)d_in[1];
    const float* wout  = (const float*)d_in[2];
    const float* fcos  = (const float*)d_in[3];
    const float* fsin  = (const float*)d_in[4];
    float* out = (float*)d_out;

    __nv_bfloat16 *qh, *ql, *kh, *kl, *vh, *vl;
    char *xa0, *xa1, *w1b0, *w1b1, *w2b0, *w2b1, *oa0, *oa1;
    float* o_p;
    cudaGetSymbolAddress((void**)&qh, g_qhi);
    cudaGetSymbolAddress((void**)&ql, g_qlo);
    cudaGetSymbolAddress((void**)&kh, g_khi);
    cudaGetSymbolAddress((void**)&kl, g_klo);
    cudaGetSymbolAddress((void**)&vh, g_vhi);
    cudaGetSymbolAddress((void**)&vl, g_vlo);
    cudaGetSymbolAddress((void**)&xa0, g_xa0);
    cudaGetSymbolAddress((void**)&xa1, g_xa1);
    cudaGetSymbolAddress((void**)&w1b0, g_w1b0);
    cudaGetSymbolAddress((void**)&w1b1, g_w1b1);
    cudaGetSymbolAddress((void**)&w2b0, g_w2b0);
    cudaGetSymbolAddress((void**)&w2b1, g_w2b1);
    cudaGetSymbolAddress((void**)&oa0, g_oa0);
    cudaGetSymbolAddress((void**)&oa1, g_oa1);
    cudaGetSymbolAddress((void**)&o_p, g_o);

    cudaFuncSetAttribute(imma_gemm_t<0>,
                         cudaFuncAttributeMaxDynamicSharedMemorySize, IGEMM_SMEM);
    cudaFuncSetAttribute(imma_gemm_t<1>,
                         cudaFuncAttributeMaxDynamicSharedMemorySize, IGEMM_SMEM);
    cudaFuncSetAttribute(flash_mma,
                         cudaFuncAttributeMaxDynamicSharedMemorySize, FLASH_SMEM);

    const int nx  = M1 * DDIM / 4;
    const int nw1 = N1 * DDIM / 4;
    const int nw2 = DDIM * DDIM / 4;

    // scales + quantization
    reset_scales<<<1, 32>>>();
    maxabs_kernel<<<1024, 256>>>(x, nx, 0);
    maxabs_kernel<<<1024, 256>>>(wqkv, nw1, 1);
    maxabs_kernel<<<1024, 256>>>(wout, nw2, 2);
    quant_kernel<<<(nx + 255) / 256, 256>>>(x, xa0, xa1, nx, 0);
    quant_kernel<<<(nw1 + 255) / 256, 256>>>(wqkv, w1b0, w1b1, nw1, 1);
    quant_kernel<<<(nw2 + 255) / 256, 256>>>(wout, w2b0, w2b1, nw2, 2);

    // 1) QKV projection (int8 IMMA) with fused dequant+RoPE+split epilogue
    imma_gemm_t<1><<<dim3(N1 / 64, M1 / 128), 256, IGEMM_SMEM>>>(
        xa0, xa1, w1b0, w1b1, nullptr, N1, DDIM, 0, 1, fcos, fsin);

    // 2) Flash attention (bf16 mma.sync) -> fp32 g_o
    flash_mma<<<dim3(SSQ / 128, FB), 256, FLASH_SMEM>>>(
        qh, ql, kh, kl, vh, vl, o_p);

    // 3) quantize attention output, then output projection (int8 IMMA)
    maxabs_kernel<<<1024, 256>>>(o_p, nx, 3);
    quant_kernel<<<(nx + 255) / 256, 256>>>(o_p, oa0, oa1, nx, 3);
    imma_gemm_t<0><<<dim3(DDIM / 64, M1 / 128), 256, IGEMM_SMEM>>>(
        oa0, oa1, w2b0, w2b1, out, DDIM, DDIM, 3, 2, nullptr, nullptr);
}

// round 11
// speedup vs baseline: 2.1294x; 2.0938x over previous
#include <cuda_runtime.h>
#include <cuda_bf16.h>
#include <cstdint>

// Problem constants
#define BB 2
#define SSQ 2048
#define DDIM 2048
#define HH 16
#define M1 (BB * SSQ)      // 4096
#define N1 (3 * DDIM)      // 6144
#define FB (BB * HH)       // 32 (b,h) pairs

// ---------------------------------------------------------------------------
// Scratch (__device__ globals: allocation-free rule)
// ---------------------------------------------------------------------------
__device__ __nv_bfloat16 g_xhi[(size_t)M1 * DDIM];
__device__ __nv_bfloat16 g_xlo[(size_t)M1 * DDIM];
__device__ __nv_bfloat16 g_whi[(size_t)N1 * DDIM];
__device__ __nv_bfloat16 g_wlo[(size_t)N1 * DDIM];
__device__ __nv_bfloat16 g_ahi[(size_t)M1 * DDIM];
__device__ __nv_bfloat16 g_alo[(size_t)M1 * DDIM];
__device__ __nv_bfloat16 g_uhi[(size_t)DDIM * DDIM];
__device__ __nv_bfloat16 g_ulo[(size_t)DDIM * DDIM];
// flash operands, layout [bh][s][128], bf16 hi/lo
__device__ __nv_bfloat16 g_qhi[(size_t)FB * SSQ * 128];
__device__ __nv_bfloat16 g_qlo[(size_t)FB * SSQ * 128];
__device__ __nv_bfloat16 g_khi[(size_t)FB * SSQ * 128];
__device__ __nv_bfloat16 g_klo[(size_t)FB * SSQ * 128];
__device__ __nv_bfloat16 g_vhi[(size_t)FB * SSQ * 128];
__device__ __nv_bfloat16 g_vlo[(size_t)FB * SSQ * 128];

__device__ __forceinline__ uint32_t smem_u32(const void* p) {
    uint32_t a;
    asm("{ .reg .u64 t; cvta.to.shared.u64 t, %1; cvt.u32.u64 %0, t; }"
        : "=r"(a) : "l"(p));
    return a;
}

#define LDMX4(R, A) \
    asm volatile("ldmatrix.sync.aligned.m8n8.x4.shared.b16 {%0,%1,%2,%3}, [%4];" \
        : "=r"((R)[0]), "=r"((R)[1]), "=r"((R)[2]), "=r"((R)[3]) : "r"(A))
#define LDMX4T(R, A) \
    asm volatile("ldmatrix.sync.aligned.m8n8.x4.trans.shared.b16 {%0,%1,%2,%3}, [%4];" \
        : "=r"((R)[0]), "=r"((R)[1]), "=r"((R)[2]), "=r"((R)[3]) : "r"(A))

#define MMA_BF16(ac, a, b0v, b1v) \
    asm volatile("mma.sync.aligned.m16n8k16.row.col.f32.bf16.bf16.f32 " \
        "{%0,%1,%2,%3},{%4,%5,%6,%7},{%8,%9},{%0,%1,%2,%3};" \
        : "+f"((ac)[0]), "+f"((ac)[1]), "+f"((ac)[2]), "+f"((ac)[3]) \
        : "r"((a)[0]), "r"((a)[1]), "r"((a)[2]), "r"((a)[3]), \
          "r"(b0v), "r"(b1v))

#define CP_ASYNC16(s, g) \
    asm volatile("cp.async.cg.shared.global [%0], [%1], 16;" :: "r"(s), "l"(g))
#define CP_COMMIT() asm volatile("cp.async.commit_group;" ::: "memory")
#define CP_WAIT1()  asm volatile("cp.async.wait_group 1;" ::: "memory")
#define CP_WAIT0()  asm volatile("cp.async.wait_group 0;" ::: "memory")

// split fp32 pair -> packed bf16x2 (hi) + packed bf16x2 (lo residual)
__device__ __forceinline__ void split_pack(float x, float y,
                                           uint32_t& hi, uint32_t& lo) {
    __nv_bfloat162 h = __floats2bfloat162_rn(x, y);
    hi = *reinterpret_cast<uint32_t*>(&h);
    __nv_bfloat162 l = __floats2bfloat162_rn(x - __low2float(h),
                                             y - __high2float(h));
    lo = *reinterpret_cast<uint32_t*>(&l);
}
__device__ __forceinline__ void split_write(__nv_bfloat16* hi_arr,
                                            __nv_bfloat16* lo_arr,
                                            size_t o, float x, float y) {
    uint32_t hi, lo;
    split_pack(x, y, hi, lo);
    *(uint32_t*)(hi_arr + o) = hi;
    *(uint32_t*)(lo_arr + o) = lo;
}

// ---------------------------------------------------------------------------
// fp32 -> (bf16 hi, bf16 lo) split (for GEMM operands)
// ---------------------------------------------------------------------------
__global__ __launch_bounds__(256) void split_bf16(
    const float* __restrict__ src, __nv_bfloat16* __restrict__ hi,
    __nv_bfloat16* __restrict__ lo, int n4)
{
    int i = blockIdx.x * blockDim.x + threadIdx.x;
    if (i >= n4) return;
    float4 v = ((const float4*)src)[i];
    uint32_t h0, l0, h1, l1;
    split_pack(v.x, v.y, h0, l0);
    split_pack(v.z, v.w, h1, l1);
    ((uint32_t*)hi)[i * 2 + 0] = h0;
    ((uint32_t*)hi)[i * 2 + 1] = h1;
    ((uint32_t*)lo)[i * 2 + 0] = l0;
    ((uint32_t*)lo)[i * 2 + 1] = l1;
}

// ---------------------------------------------------------------------------
// mma.sync GEMM, 3-term bf16 split. CTA 128x256, 256 threads (8 warps,
// warp tile 64x64), k-chunk 32, 3-stage cp.async pipeline, 1 barrier/iter.
// MMA:LDSM = 6:1 (was 2:1) to relieve issue-slot / shared-pipe pressure.
//  MODE 0: plain fp32 store to C
//  MODE 1: fused RoPE + relayout + bf16 split into g_q/k/v hi/lo (QKV GEMM)
// ---------------------------------------------------------------------------
#define KC 32
#define AST 40                         // padded row stride (bf16 elems, 80 B)
#define A_T   10240                    // A digit tile bytes: 128*40*2
#define B_T   20480                    // B digit tile bytes: 256*40*2
#define B_OFF (2 * A_T)                // 20480
#define STAGE_B (2 * A_T + 2 * B_T)    // 61440
#define GEMM_SMEM (3 * STAGE_B)        // 184320

template <int MODE>
__global__ __launch_bounds__(256, 1) void mma_gemm_t(
    const __nv_bfloat16* __restrict__ Ahi, const __nv_bfloat16* __restrict__ Alo,
    const __nv_bfloat16* __restrict__ Bhi, const __nv_bfloat16* __restrict__ Blo,
    float* __restrict__ C, int Ntot, int K,
    const float* __restrict__ fc, const float* __restrict__ fs)
{
    extern __shared__ __nv_bfloat16 smb[];
    const uint32_t sbase = smem_u32(smb);
    const int t = threadIdx.x;
    const int lane = t & 31, warp = t >> 5;
    const int bm = blockIdx.y << 7;      // 128-row tiles
    const int bn = blockIdx.x << 8;      // 256-col tiles
    const int wm = (warp >> 2) << 6;     // 0 / 64
    const int wn = (warp & 3) << 6;      // 0,64,128,192

    // loader mapping
    const int rA  = t >> 1;              // 0..127
    const int cA0 = (t & 1) << 1;        // chunk base 0 or 2 (of 4/row)
    const int rB  = t;                   // 0..255

    const __nv_bfloat16* gAh = Ahi + (size_t)(bm + rA) * K + cA0 * 8;
    const __nv_bfloat16* gAl = Alo + (size_t)(bm + rA) * K + cA0 * 8;
    const __nv_bfloat16* gBh = Bhi + (size_t)(bn + rB) * K;
    const __nv_bfloat16* gBl = Blo + (size_t)(bn + rB) * K;

    const uint32_t sAh = sbase + (rA * AST + cA0 * 8) * 2;
    const uint32_t sAl = sAh + A_T;
    const uint32_t sBh = sbase + B_OFF + rB * AST * 2;
    const uint32_t sBl = sBh + B_T;

    auto load_stage = [&](int kc, int buf) {
        const uint32_t so = buf * STAGE_B;
        const int go = kc * KC;
        CP_ASYNC16(sAh + so,      gAh + go);
        CP_ASYNC16(sAh + so + 16, gAh + go + 8);
        CP_ASYNC16(sAl + so,      gAl + go);
        CP_ASYNC16(sAl + so + 16, gAl + go + 8);
#pragma unroll
        for (int c = 0; c < 4; c++) {
            CP_ASYNC16(sBh + so + c * 16, gBh + go + c * 8);
            CP_ASYNC16(sBl + so + c * 16, gBl + go + c * 8);
        }
        CP_COMMIT();
    };

    float acc[4][8][4] = {};
    const int NIT = K / KC;

    load_stage(0, 0);
    load_stage(1, 1);

    const int ldrow = lane & 15;
    const int ldcol = (lane >> 4) << 3;

    int buf = 0;
    for (int it = 0; it < NIT; it++) {
        CP_WAIT1();
        __syncthreads();
        if (it + 2 < NIT) {
            int nb = buf + 2; if (nb >= 3) nb -= 3;
            load_stage(it + 2, nb);
        }

        const uint32_t sb = sbase + buf * STAGE_B;
#pragma unroll
        for (int kh = 0; kh < 2; kh++) {
            uint32_t aH[4][4], aL[4][4], bH[8][2], bL[8][2];
            const int colb = (kh * 16 + ldcol) * 2;
#pragma unroll
            for (int mt = 0; mt < 4; mt++) {
                uint32_t ra = sb + (wm + mt * 16 + ldrow) * (AST * 2) + colb;
                LDMX4(aH[mt], ra);
                LDMX4(aL[mt], ra + A_T);
            }
#pragma unroll
            for (int n2 = 0; n2 < 4; n2++) {
                uint32_t rb = sb + B_OFF +
                              (wn + n2 * 16 + ldrow) * (AST * 2) + colb;
                uint32_t r[4];
                LDMX4(r, rb);
                bH[n2 * 2 + 0][0] = r[0]; bH[n2 * 2 + 0][1] = r[2];
                bH[n2 * 2 + 1][0] = r[1]; bH[n2 * 2 + 1][1] = r[3];
                LDMX4(r, rb + B_T);
                bL[n2 * 2 + 0][0] = r[0]; bL[n2 * 2 + 0][1] = r[2];
                bL[n2 * 2 + 1][0] = r[1]; bL[n2 * 2 + 1][1] = r[3];
            }
#pragma unroll
            for (int mt = 0; mt < 4; mt++) {
#pragma unroll
                for (int nt = 0; nt < 8; nt++) {
                    MMA_BF16(acc[mt][nt], aH[mt], bH[nt][0], bH[nt][1]);
                    MMA_BF16(acc[mt][nt], aH[mt], bL[nt][0], bL[nt][1]);
                    MMA_BF16(acc[mt][nt], aL[mt], bH[nt][0], bH[nt][1]);
                }
            }
        }
        buf++; if (buf == 3) buf = 0;
    }

    const int grp = lane >> 2, qq = (lane & 3) << 1;

    if (MODE == 0) {
#pragma unroll
        for (int mt = 0; mt < 4; mt++) {
#pragma unroll
            for (int nt = 0; nt < 8; nt++) {
                float* p = C + (size_t)(bm + wm + mt * 16 + grp) * Ntot
                             + bn + wn + nt * 8 + qq;
                *(float2*)p = make_float2(acc[mt][nt][0], acc[mt][nt][1]);
                *(float2*)(p + (size_t)8 * Ntot) =
                    make_float2(acc[mt][nt][2], acc[mt][nt][3]);
            }
        }
    } else {
        // fused RoPE + relayout + split; CTA-uniform region (q/k/v)
        const int region = bn >> 11;            // 0=q, 1=k, 2=v
        const float scale = 0.08838834764831845f; // 1/sqrt(128)
#pragma unroll
        for (int mt = 0; mt < 4; mt++) {
            const int r0 = bm + wm + mt * 16 + grp;
            const int b  = r0 >> 11;
            const int s0 = r0 & (SSQ - 1);
            const int s1 = s0 + 8;
#pragma unroll
            for (int nt = 0; nt < 8; nt++) {
                const int c  = bn + wn + nt * 8 + qq;
                const int cr = c & (DDIM - 1);
                const int h  = cr >> 7;
                const int ch = cr & 127;
                const int i  = ch >> 1;
                const size_t ob = ((size_t)(b * HH + h) * SSQ);
                const size_t o0 = (ob + s0) * 128 + ch;
                const size_t o1 = (ob + s1) * 128 + ch;
                float x0 = acc[mt][nt][0], y0 = acc[mt][nt][1];
                float x1 = acc[mt][nt][2], y1 = acc[mt][nt][3];
                if (region == 2) {
                    split_write(g_vhi, g_vlo, o0, x0, y0);
                    split_write(g_vhi, g_vlo, o1, x1, y1);
                } else {
                    float c0 = fc[(s0 << 6) + i], sn0 = fs[(s0 << 6) + i];
                    float c1 = fc[(s1 << 6) + i], sn1 = fs[(s1 << 6) + i];
                    float rx0 = x0 * c0 - y0 * sn0, ry0 = x0 * sn0 + y0 * c0;
                    float rx1 = x1 * c1 - y1 * sn1, ry1 = x1 * sn1 + y1 * c1;
                    if (region == 0) {
                        split_write(g_qhi, g_qlo, o0, rx0 * scale, ry0 * scale);
                        split_write(g_qhi, g_qlo, o1, rx1 * scale, ry1 * scale);
                    } else {
                        split_write(g_khi, g_klo, o0, rx0, ry0);
                        split_write(g_khi, g_klo, o1, rx1, ry1);
                    }
                }
            }
        }
    }
}

// ---------------------------------------------------------------------------
// Flash attention on mma.sync (bf16 3-term split, fp32 softmax).
// Writes bf16 hi/lo output directly (input to GEMM2).
// ---------------------------------------------------------------------------
#define FSTR 136
#define FTILE (64 * FSTR)
#define QTILE (128 * FSTR)
#define FLASH_SMEM ((2 * QTILE + 8 * FTILE) * 2)   // 208896 bytes

__global__ __launch_bounds__(256, 1) void flash_mma(
    const __nv_bfloat16* __restrict__ qhi, const __nv_bfloat16* __restrict__ qlo,
    const __nv_bfloat16* __restrict__ khi, const __nv_bfloat16* __restrict__ klo,
    const __nv_bfloat16* __restrict__ vhi, const __nv_bfloat16* __restrict__ vlo,
    __nv_bfloat16* __restrict__ ohi, __nv_bfloat16* __restrict__ olo)
{
    extern __shared__ __nv_bfloat16 fsm[];
    const uint32_t sb = smem_u32(fsm);
    const int t = threadIdx.x;
    const int lane = t & 31, warp = t >> 5;
    const int qt = (int)gridDim.x - 1 - (int)blockIdx.x;
    const int bh = blockIdx.y;
    const int q0 = qt << 7;
    const size_t bhbase = (size_t)bh * SSQ * 128;

    const int ldr = lane & 15;
    const int ldc = (lane >> 4) << 3;
    const int grp = lane >> 2;
    const int qq  = (lane & 3) << 1;

    {
        int r = t >> 1;
        int e0 = (t & 1) << 6;
        const __nv_bfloat16* srcs[2] = {
            qhi + bhbase + (size_t)(q0 + r) * 128 + e0,
            qlo + bhbase + (size_t)(q0 + r) * 128 + e0 };
        uint32_t s0 = sb + (r * FSTR + e0) * 2;
#pragma unroll
        for (int tile = 0; tile < 2; tile++)
#pragma unroll
            for (int c = 0; c < 8; c++)
                CP_ASYNC16(s0 + tile * QTILE * 2 + c * 16, srcs[tile] + c * 8);
        CP_COMMIT();
    }

    auto load_kv = [&](int kt, int buf) {
        int r = t >> 2;
        int e0 = (t & 3) << 5;
        size_t g0 = bhbase + (size_t)(kt * 64 + r) * 128 + e0;
        const __nv_bfloat16* srcs[4] = { khi + g0, klo + g0, vhi + g0, vlo + g0 };
        uint32_t s0 = sb + (2 * QTILE + buf * 4 * FTILE + r * FSTR + e0) * 2;
#pragma unroll
        for (int tile = 0; tile < 4; tile++)
#pragma unroll
            for (int c = 0; c < 4; c++)
                CP_ASYNC16(s0 + tile * FTILE * 2 + c * 16, srcs[tile] + c * 8);
        CP_COMMIT();
    };

    CP_WAIT0();
    __syncthreads();
    uint32_t qh[8][4], ql[8][4];
    const int wrow = warp << 4;
#pragma unroll
    for (int d = 0; d < 8; d++) {
        uint32_t a = sb + ((wrow + ldr) * FSTR + d * 16 + ldc) * 2;
        LDMX4(qh[d], a);
        LDMX4(ql[d], a + QTILE * 2);
    }

    const int ktmax = 2 * qt + 1;
    load_kv(0, 0);
    load_kv(1, 1);

    float Of[16][4] = {};
    float m0 = -1e30f, m1 = -1e30f, l0 = 0.f, l1 = 0.f;

    for (int kt = 0; kt <= ktmax; kt++) {
        if (kt == ktmax) { CP_WAIT0(); } else { CP_WAIT1(); }
        __syncthreads();

        const uint32_t kvb = sb + (2 * QTILE + (kt & 1) * 4 * FTILE) * 2;

        float Sf[8][4] = {};
#pragma unroll
        for (int d = 0; d < 8; d++) {
#pragma unroll
            for (int n4 = 0; n4 < 4; n4++) {
                uint32_t addr = kvb + ((n4 * 16 + ldr) * FSTR + d * 16 + ldc) * 2;
                uint32_t kb0[4], kb1[4];
                LDMX4(kb0, addr);
                LDMX4(kb1, addr + FTILE * 2);
                MMA_BF16(Sf[2 * n4],     qh[d], kb0[0], kb0[2]);
                MMA_BF16(Sf[2 * n4 + 1], qh[d], kb0[1], kb0[3]);
                MMA_BF16(Sf[2 * n4],     qh[d], kb1[0], kb1[2]);
                MMA_BF16(Sf[2 * n4 + 1], qh[d], kb1[1], kb1[3]);
                MMA_BF16(Sf[2 * n4],     ql[d], kb0[0], kb0[2]);
                MMA_BF16(Sf[2 * n4 + 1], ql[d], kb0[1], kb0[3]);
            }
        }

        const int r0 = q0 + wrow + grp;
        if (kt >= 2 * qt) {
#pragma unroll
            for (int nb = 0; nb < 8; nb++) {
#pragma unroll
                for (int j = 0; j < 2; j++) {
                    int key = kt * 64 + nb * 8 + qq + j;
                    if (key > r0)     Sf[nb][j]     = -1e30f;
                    if (key > r0 + 8) Sf[nb][2 + j] = -1e30f;
                }
            }
        }

        float mx0 = -1e30f, mx1 = -1e30f;
#pragma unroll
        for (int nb = 0; nb < 8; nb++) {
            mx0 = fmaxf(mx0, fmaxf(Sf[nb][0], Sf[nb][1]));
            mx1 = fmaxf(mx1, fmaxf(Sf[nb][2], Sf[nb][3]));
        }
        mx0 = fmaxf(mx0, __shfl_xor_sync(0xffffffff, mx0, 1));
        mx0 = fmaxf(mx0, __shfl_xor_sync(0xffffffff, mx0, 2));
        mx1 = fmaxf(mx1, __shfl_xor_sync(0xffffffff, mx1, 1));
        mx1 = fmaxf(mx1, __shfl_xor_sync(0xffffffff, mx1, 2));
        float mn0 = fmaxf(m0, mx0), mn1 = fmaxf(m1, mx1);
        float a0 = __expf(m0 - mn0), a1 = __expf(m1 - mn1);
        float s0 = 0.f, s1 = 0.f;
#pragma unroll
        for (int nb = 0; nb < 8; nb++) {
            Sf[nb][0] = __expf(Sf[nb][0] - mn0); s0 += Sf[nb][0];
            Sf[nb][1] = __expf(Sf[nb][1] - mn0); s0 += Sf[nb][1];
            Sf[nb][2] = __expf(Sf[nb][2] - mn1); s1 += Sf[nb][2];
            Sf[nb][3] = __expf(Sf[nb][3] - mn1); s1 += Sf[nb][3];
        }
        s0 += __shfl_xor_sync(0xffffffff, s0, 1);
        s0 += __shfl_xor_sync(0xffffffff, s0, 2);
        s1 += __shfl_xor_sync(0xffffffff, s1, 1);
        s1 += __shfl_xor_sync(0xffffffff, s1, 2);
        l0 = l0 * a0 + s0;  l1 = l1 * a1 + s1;
        m0 = mn0;           m1 = mn1;
#pragma unroll
        for (int nb = 0; nb < 16; nb++) {
            Of[nb][0] *= a0; Of[nb][1] *= a0;
            Of[nb][2] *= a1; Of[nb][3] *= a1;
        }

        const uint32_t vb = kvb + 2 * FTILE * 2;
#pragma unroll
        for (int j = 0; j < 4; j++) {
            uint32_t ph[4], pl[4];
            split_pack(Sf[2 * j][0],     Sf[2 * j][1],     ph[0], pl[0]);
            split_pack(Sf[2 * j][2],     Sf[2 * j][3],     ph[1], pl[1]);
            split_pack(Sf[2 * j + 1][0], Sf[2 * j + 1][1], ph[2], pl[2]);
            split_pack(Sf[2 * j + 1][2], Sf[2 * j + 1][3], ph[3], pl[3]);
#pragma unroll
            for (int nb2 = 0; nb2 < 8; nb2++) {
                uint32_t addr = vb + ((j * 16 + ldr) * FSTR + nb2 * 16 + ldc) * 2;
                uint32_t vh[4], vl[4];
                LDMX4T(vh, addr);
                LDMX4T(vl, addr + FTILE * 2);
                MMA_BF16(Of[2 * nb2],     ph, vh[0], vh[1]);
                MMA_BF16(Of[2 * nb2 + 1], ph, vh[2], vh[3]);
                MMA_BF16(Of[2 * nb2],     ph, vl[0], vl[1]);
                MMA_BF16(Of[2 * nb2 + 1], ph, vl[2], vl[3]);
                MMA_BF16(Of[2 * nb2],     pl, vh[0], vh[1]);
                MMA_BF16(Of[2 * nb2 + 1], pl, vh[2], vh[3]);
            }
        }

        __syncthreads();
        if (kt + 2 <= ktmax) load_kv(kt + 2, kt & 1);
    }

    const int b = bh >> 4, h = bh & 15;
    const float inv0 = 1.0f / l0, inv1 = 1.0f / l1;
    const size_t row0 = (size_t)(b * SSQ + q0 + wrow + grp) * DDIM + (h << 7);
    const size_t row1 = row0 + (size_t)8 * DDIM;
#pragma unroll
    for (int nb = 0; nb < 16; nb++) {
        size_t o = row0 + nb * 8 + qq;
        split_write(ohi, olo, o, Of[nb][0] * inv0, Of[nb][1] * inv0);
        o = row1 + nb * 8 + qq;
        split_write(ohi, olo, o, Of[nb][2] * inv1, Of[nb][3] * inv1);
    }
}

// ---------------------------------------------------------------------------
// Launch
// ---------------------------------------------------------------------------
extern "C" void kernel_launch(void* const* d_in, const int* in_sizes, int n_in,
                              void* d_out, int out_size)
{
    const float* x     = (const float*)d_in[0];
    const float* wqkv  = (const float*)d_in[1];
    const float* wout  = (const float*)d_in[2];
    const float* fcos  = (const float*)d_in[3];
    const float* fsin  = (const float*)d_in[4];
    float* out = (float*)d_out;

    __nv_bfloat16 *xhi, *xlo, *whi, *wlo, *ahi, *alo, *uhi, *ulo;
    __nv_bfloat16 *qh, *ql, *kh, *kl, *vh, *vl;
    cudaGetSymbolAddress((void**)&xhi, g_xhi);
    cudaGetSymbolAddress((void**)&xlo, g_xlo);
    cudaGetSymbolAddress((void**)&whi, g_whi);
    cudaGetSymbolAddress((void**)&wlo, g_wlo);
    cudaGetSymbolAddress((void**)&ahi, g_ahi);
    cudaGetSymbolAddress((void**)&alo, g_alo);
    cudaGetSymbolAddress((void**)&uhi, g_uhi);
    cudaGetSymbolAddress((void**)&ulo, g_ulo);
    cudaGetSymbolAddress((void**)&qh, g_qhi);
    cudaGetSymbolAddress((void**)&ql, g_qlo);
    cudaGetSymbolAddress((void**)&kh, g_khi);
    cudaGetSymbolAddress((void**)&kl, g_klo);
    cudaGetSymbolAddress((void**)&vh, g_vhi);
    cudaGetSymbolAddress((void**)&vl, g_vlo);

    cudaFuncSetAttribute(mma_gemm_t<0>,
                         cudaFuncAttributeMaxDynamicSharedMemorySize, GEMM_SMEM);
    cudaFuncSetAttribute(mma_gemm_t<1>,
                         cudaFuncAttributeMaxDynamicSharedMemorySize, GEMM_SMEM);
    cudaFuncSetAttribute(flash_mma,
                         cudaFuncAttributeMaxDynamicSharedMemorySize, FLASH_SMEM);

    // operand splits
    split_bf16<<<(M1 * DDIM / 4) / 256, 256>>>(x, xhi, xlo, M1 * DDIM / 4);
    split_bf16<<<(N1 * DDIM / 4) / 256, 256>>>(wqkv, whi, wlo, N1 * DDIM / 4);
    split_bf16<<<(DDIM * DDIM / 4) / 256, 256>>>(wout, uhi, ulo, DDIM * DDIM / 4);

    // 1) QKV projection with fused RoPE + split epilogue
    mma_gemm_t<1><<<dim3(N1 / 256, M1 / 128), 256, GEMM_SMEM>>>(
        xhi, xlo, whi, wlo, nullptr, N1, DDIM, fcos, fsin);

    // 2) Flash attention (mma.sync) -> writes g_ahi/g_alo directly
    flash_mma<<<dim3(SSQ / 128, FB), 256, FLASH_SMEM>>>(
        qh, ql, kh, kl, vh, vl, ahi, alo);

    // 3) Output projection
    mma_gemm_t<0><<<dim3(DDIM / 256, M1 / 128), 256, GEMM_SMEM>>>(
        ahi, alo, uhi, ulo, out, DDIM, DDIM, nullptr, nullptr);
}

// round 12
// speedup vs baseline: 3.3495x; 1.5730x over previous
#include <cuda_runtime.h>
#include <cuda_fp16.h>
#include <cstdint>

// Problem constants
#define BB 2
#define SSQ 2048
#define DDIM 2048
#define HH 16
#define M1 (BB * SSQ)      // 4096
#define N1 (3 * DDIM)      // 6144
#define FB (BB * HH)       // 32 (b,h) pairs

// ---------------------------------------------------------------------------
// Scratch (__device__ globals: allocation-free rule). All fp16.
// A-operands are 1-digit, B-operands are 2-digit (hi+lo).
// ---------------------------------------------------------------------------
__device__ __half g_xh  [(size_t)M1 * DDIM];          // GEMM1 A (1-digit)
__device__ __half g_w1hi[(size_t)N1 * DDIM];          // GEMM1 B hi
__device__ __half g_w1lo[(size_t)N1 * DDIM];          // GEMM1 B lo
__device__ __half g_w2hi[(size_t)DDIM * DDIM];        // GEMM2 B hi
__device__ __half g_w2lo[(size_t)DDIM * DDIM];        // GEMM2 B lo
__device__ __half g_ah  [(size_t)M1 * DDIM];          // GEMM2 A (flash out)
// flash operands, layout [bh][s][128]
__device__ __half g_qh [(size_t)FB * SSQ * 128];      // Q (1-digit)
__device__ __half g_khi[(size_t)FB * SSQ * 128];
__device__ __half g_klo[(size_t)FB * SSQ * 128];
__device__ __half g_vhi[(size_t)FB * SSQ * 128];
__device__ __half g_vlo[(size_t)FB * SSQ * 128];

__device__ __forceinline__ uint32_t smem_u32(const void* p) {
    uint32_t a;
    asm("{ .reg .u64 t; cvta.to.shared.u64 t, %1; cvt.u32.u64 %0, t; }"
        : "=r"(a) : "l"(p));
    return a;
}

#define LDMX4(R, A) \
    asm volatile("ldmatrix.sync.aligned.m8n8.x4.shared.b16 {%0,%1,%2,%3}, [%4];" \
        : "=r"((R)[0]), "=r"((R)[1]), "=r"((R)[2]), "=r"((R)[3]) : "r"(A))
#define LDMX4T(R, A) \
    asm volatile("ldmatrix.sync.aligned.m8n8.x4.trans.shared.b16 {%0,%1,%2,%3}, [%4];" \
        : "=r"((R)[0]), "=r"((R)[1]), "=r"((R)[2]), "=r"((R)[3]) : "r"(A))

#define MMA_F16(ac, a, b0v, b1v) \
    asm volatile("mma.sync.aligned.m16n8k16.row.col.f32.f16.f16.f32 " \
        "{%0,%1,%2,%3},{%4,%5,%6,%7},{%8,%9},{%0,%1,%2,%3};" \
        : "+f"((ac)[0]), "+f"((ac)[1]), "+f"((ac)[2]), "+f"((ac)[3]) \
        : "r"((a)[0]), "r"((a)[1]), "r"((a)[2]), "r"((a)[3]), \
          "r"(b0v), "r"(b1v))

#define CP_ASYNC16(s, g) \
    asm volatile("cp.async.cg.shared.global [%0], [%1], 16;" :: "r"(s), "l"(g))
#define CP_COMMIT() asm volatile("cp.async.commit_group;" ::: "memory")
#define CP_WAIT1()  asm volatile("cp.async.wait_group 1;" ::: "memory")
#define CP_WAIT0()  asm volatile("cp.async.wait_group 0;" ::: "memory")

// pack two floats to half2 bits
__device__ __forceinline__ uint32_t pack_h2(float x, float y) {
    __half2 h = __floats2half2_rn(x, y);
    return *reinterpret_cast<uint32_t*>(&h);
}
// split fp32 pair -> fp16 hi pair + fp16 lo (residual) pair
__device__ __forceinline__ void split_h2(float x, float y,
                                         uint32_t& hi, uint32_t& lo) {
    __half2 h = __floats2half2_rn(x, y);
    hi = *reinterpret_cast<uint32_t*>(&h);
    __half2 l = __floats2half2_rn(x - __low2float(h), y - __high2float(h));
    lo = *reinterpret_cast<uint32_t*>(&l);
}
__device__ __forceinline__ void split_write_h(__half* hi_arr, __half* lo_arr,
                                              size_t o, float x, float y) {
    uint32_t hi, lo;
    split_h2(x, y, hi, lo);
    *(uint32_t*)(hi_arr + o) = hi;
    *(uint32_t*)(lo_arr + o) = lo;
}

// ---------------------------------------------------------------------------
// fp32 -> fp16 convert (1-digit) and fp32 -> fp16 hi/lo split (2-digit)
// ---------------------------------------------------------------------------
__global__ __launch_bounds__(256) void cvt_h(
    const float* __restrict__ src, __half* __restrict__ dst, int n4)
{
    int i = blockIdx.x * blockDim.x + threadIdx.x;
    if (i >= n4) return;
    float4 v = ((const float4*)src)[i];
    ((uint32_t*)dst)[i * 2 + 0] = pack_h2(v.x, v.y);
    ((uint32_t*)dst)[i * 2 + 1] = pack_h2(v.z, v.w);
}

__global__ __launch_bounds__(256) void split_h(
    const float* __restrict__ src, __half* __restrict__ hi,
    __half* __restrict__ lo, int n4)
{
    int i = blockIdx.x * blockDim.x + threadIdx.x;
    if (i >= n4) return;
    float4 v = ((const float4*)src)[i];
    uint32_t h0, l0, h1, l1;
    split_h2(v.x, v.y, h0, l0);
    split_h2(v.z, v.w, h1, l1);
    ((uint32_t*)hi)[i * 2 + 0] = h0;
    ((uint32_t*)hi)[i * 2 + 1] = h1;
    ((uint32_t*)lo)[i * 2 + 0] = l0;
    ((uint32_t*)lo)[i * 2 + 1] = l1;
}

// ---------------------------------------------------------------------------
// mma.sync fp16 GEMM:  C[M,N] = A[M,K] * W[N,K]^T, A 1-digit, W 2-digit.
// 2 MMAs per (16k x 8n) tile (A*Whi + A*Wlo). CTA 128x128, 256 threads
// (8 warps, warp tile 64x32), k-chunk 32, double-buffered cp.async.
//  MODE 0: plain fp32 store to C
//  MODE 1: fused RoPE + relayout into flash operands (q 1-digit, k/v 2-digit)
// ---------------------------------------------------------------------------
#define KC 32
#define AST 40                           // padded row stride (fp16 elems, 80 B)
#define TILE_B 10240                     // one 128x32 tile: 128*40*2 bytes
#define STAGE_B (3 * TILE_B)             // A, Bhi, Blo = 30720 B
#define GEMM_SMEM (2 * STAGE_B)          // 61440 B

template <int MODE>
__global__ __launch_bounds__(256, 2) void mma_gemm_t(
    const __half* __restrict__ A, const __half* __restrict__ Bhi,
    const __half* __restrict__ Blo, float* __restrict__ C, int Ntot, int K,
    const float* __restrict__ fc, const float* __restrict__ fs)
{
    extern __shared__ __half smh[];
    const uint32_t sbase = smem_u32(smh);
    const int t = threadIdx.x;
    const int lane = t & 31, warp = t >> 5;
    const int bm = blockIdx.y << 7;
    const int bn = blockIdx.x << 7;
    const int wm = (warp >> 2) << 6;   // 0 / 64
    const int wn = (warp & 3) << 5;    // 0,32,64,96

    // loader mapping: row lr (0..127), chunks {lc0, lc0+1} of 4 per row
    const int lr = t >> 1;
    const int lc0 = (t & 1) << 1;

    const __half* gsrc[3] = {
        A   + (size_t)(bm + lr) * K,
        Bhi + (size_t)(bn + lr) * K,
        Blo + (size_t)(bn + lr) * K };

    auto load_stage = [&](int kc, int buf) {
        uint32_t sb = sbase + buf * STAGE_B;
#pragma unroll
        for (int tile = 0; tile < 3; tile++) {
#pragma unroll
            for (int i = 0; i < 2; i++) {
                int c = lc0 + i;
                uint32_t sa = sb + tile * TILE_B + (lr * AST + c * 8) * 2;
                const void* ga = gsrc[tile] + kc * KC + c * 8;
                CP_ASYNC16(sa, ga);
            }
        }
        CP_COMMIT();
    };

    float acc[4][4][4] = {};
    const int NIT = K / KC;

    load_stage(0, 0);

    const int ldrow = lane & 15;
    const int ldcol = (lane >> 4) << 3;

    for (int it = 0; it < NIT; it++) {
        if (it + 1 < NIT) { load_stage(it + 1, (it + 1) & 1); CP_WAIT1(); }
        else              { CP_WAIT0(); }
        __syncthreads();

        const uint32_t sb = sbase + (it & 1) * STAGE_B;
#pragma unroll
        for (int kh = 0; kh < 2; kh++) {
            uint32_t aF[4][4], bH[4][2], bL[4][2];
            const int colb = (kh * 16 + ldcol) * 2;
#pragma unroll
            for (int mt = 0; mt < 4; mt++) {
                uint32_t ra = sb + (wm + mt * 16 + ldrow) * (AST * 2) + colb;
                LDMX4(aF[mt], ra);
            }
#pragma unroll
            for (int n2 = 0; n2 < 2; n2++) {
                uint32_t rb = sb + TILE_B +
                              (wn + n2 * 16 + ldrow) * (AST * 2) + colb;
                uint32_t r[4];
                LDMX4(r, rb);
                bH[n2 * 2 + 0][0] = r[0]; bH[n2 * 2 + 0][1] = r[2];
                bH[n2 * 2 + 1][0] = r[1]; bH[n2 * 2 + 1][1] = r[3];
                LDMX4(r, rb + TILE_B);
                bL[n2 * 2 + 0][0] = r[0]; bL[n2 * 2 + 0][1] = r[2];
                bL[n2 * 2 + 1][0] = r[1]; bL[n2 * 2 + 1][1] = r[3];
            }
#pragma unroll
            for (int mt = 0; mt < 4; mt++) {
#pragma unroll
                for (int nt = 0; nt < 4; nt++) {
                    MMA_F16(acc[mt][nt], aF[mt], bH[nt][0], bH[nt][1]);
                    MMA_F16(acc[mt][nt], aF[mt], bL[nt][0], bL[nt][1]);
                }
            }
        }
        __syncthreads();
    }

    const int grp = lane >> 2, qq = (lane & 3) << 1;

    if (MODE == 0) {
#pragma unroll
        for (int mt = 0; mt < 4; mt++) {
#pragma unroll
            for (int nt = 0; nt < 4; nt++) {
                float* p = C + (size_t)(bm + wm + mt * 16 + grp) * Ntot
                             + bn + wn + nt * 8 + qq;
                *(float2*)p = make_float2(acc[mt][nt][0], acc[mt][nt][1]);
                *(float2*)(p + (size_t)8 * Ntot) =
                    make_float2(acc[mt][nt][2], acc[mt][nt][3]);
            }
        }
    } else {
        // fused RoPE + relayout; CTA-uniform region (q/k/v)
        const int region = bn >> 11;            // 0=q, 1=k, 2=v
        const float scale = 0.08838834764831845f; // 1/sqrt(128)
#pragma unroll
        for (int mt = 0; mt < 4; mt++) {
            const int r0 = bm + wm + mt * 16 + grp;
            const int b  = r0 >> 11;
            const int s0 = r0 & (SSQ - 1);
            const int s1 = s0 + 8;
#pragma unroll
            for (int nt = 0; nt < 4; nt++) {
                const int c  = bn + wn + nt * 8 + qq;
                const int cr = c & (DDIM - 1);
                const int h  = cr >> 7;
                const int ch = cr & 127;
                const int i  = ch >> 1;
                const size_t ob = ((size_t)(b * HH + h) * SSQ);
                const size_t o0 = (ob + s0) * 128 + ch;
                const size_t o1 = (ob + s1) * 128 + ch;
                float x0 = acc[mt][nt][0], y0 = acc[mt][nt][1];
                float x1 = acc[mt][nt][2], y1 = acc[mt][nt][3];
                if (region == 2) {
                    split_write_h(g_vhi, g_vlo, o0, x0, y0);
                    split_write_h(g_vhi, g_vlo, o1, x1, y1);
                } else {
                    float c0 = fc[(s0 << 6) + i], sn0 = fs[(s0 << 6) + i];
                    float c1 = fc[(s1 << 6) + i], sn1 = fs[(s1 << 6) + i];
                    float rx0 = x0 * c0 - y0 * sn0, ry0 = x0 * sn0 + y0 * c0;
                    float rx1 = x1 * c1 - y1 * sn1, ry1 = x1 * sn1 + y1 * c1;
                    if (region == 0) {
                        *(uint32_t*)(g_qh + o0) = pack_h2(rx0 * scale, ry0 * scale);
                        *(uint32_t*)(g_qh + o1) = pack_h2(rx1 * scale, ry1 * scale);
                    } else {
                        split_write_h(g_khi, g_klo, o0, rx0, ry0);
                        split_write_h(g_khi, g_klo, o1, rx1, ry1);
                    }
                }
            }
        }
    }
}

// ---------------------------------------------------------------------------
// Flash attention on fp16 mma.sync: Q 1-digit, K/V 2-digit, P 1-digit.
// QK: 4 MMAs per (d,n4) (was 6). PV: 4 MMAs per (j,nb2) (was 6).
// Writes fp16 1-digit output (GEMM2 A operand).
// ---------------------------------------------------------------------------
#define FSTR 136
#define FTILE (64 * FSTR)
#define QTILE (128 * FSTR)
#define FLASH_SMEM ((QTILE + 8 * FTILE) * 2)   // 174080 bytes

__global__ __launch_bounds__(256, 1) void flash_mma(
    const __half* __restrict__ qh_, const __half* __restrict__ khi,
    const __half* __restrict__ klo, const __half* __restrict__ vhi,
    const __half* __restrict__ vlo, __half* __restrict__ oh)
{
    extern __shared__ __half fsm[];
    const uint32_t sb = smem_u32(fsm);
    const int t = threadIdx.x;
    const int lane = t & 31, warp = t >> 5;
    const int qt = (int)gridDim.x - 1 - (int)blockIdx.x;
    const int bh = blockIdx.y;
    const int q0 = qt << 7;
    const size_t bhbase = (size_t)bh * SSQ * 128;

    const int ldr = lane & 15;
    const int ldc = (lane >> 4) << 3;
    const int grp = lane >> 2;
    const int qq  = (lane & 3) << 1;

    // stage Q (1 digit)
    {
        int r = t >> 1;
        int e0 = (t & 1) << 6;
        const __half* src = qh_ + bhbase + (size_t)(q0 + r) * 128 + e0;
        uint32_t s0 = sb + (r * FSTR + e0) * 2;
#pragma unroll
        for (int c = 0; c < 8; c++)
            CP_ASYNC16(s0 + c * 16, src + c * 8);
        CP_COMMIT();
    }

    auto load_kv = [&](int kt, int buf) {
        int r = t >> 2;
        int e0 = (t & 3) << 5;
        size_t g0 = bhbase + (size_t)(kt * 64 + r) * 128 + e0;
        const __half* srcs[4] = { khi + g0, klo + g0, vhi + g0, vlo + g0 };
        uint32_t s0 = sb + (QTILE + buf * 4 * FTILE + r * FSTR + e0) * 2;
#pragma unroll
        for (int tile = 0; tile < 4; tile++)
#pragma unroll
            for (int c = 0; c < 4; c++)
                CP_ASYNC16(s0 + tile * FTILE * 2 + c * 16, srcs[tile] + c * 8);
        CP_COMMIT();
    };

    CP_WAIT0();
    __syncthreads();
    uint32_t qf[8][4];
    const int wrow = warp << 4;
#pragma unroll
    for (int d = 0; d < 8; d++) {
        uint32_t a = sb + ((wrow + ldr) * FSTR + d * 16 + ldc) * 2;
        LDMX4(qf[d], a);
    }

    const int ktmax = 2 * qt + 1;
    load_kv(0, 0);
    load_kv(1, 1);

    float Of[16][4] = {};
    float m0 = -1e30f, m1 = -1e30f, l0 = 0.f, l1 = 0.f;

    for (int kt = 0; kt <= ktmax; kt++) {
        if (kt == ktmax) { CP_WAIT0(); } else { CP_WAIT1(); }
        __syncthreads();

        const uint32_t kvb = sb + (QTILE + (kt & 1) * 4 * FTILE) * 2;

        float Sf[8][4] = {};
#pragma unroll
        for (int d = 0; d < 8; d++) {
#pragma unroll
            for (int n4 = 0; n4 < 4; n4++) {
                uint32_t addr = kvb + ((n4 * 16 + ldr) * FSTR + d * 16 + ldc) * 2;
                uint32_t kb0[4], kb1[4];
                LDMX4(kb0, addr);              // Khi
                LDMX4(kb1, addr + FTILE * 2);  // Klo
                MMA_F16(Sf[2 * n4],     qf[d], kb0[0], kb0[2]);
                MMA_F16(Sf[2 * n4 + 1], qf[d], kb0[1], kb0[3]);
                MMA_F16(Sf[2 * n4],     qf[d], kb1[0], kb1[2]);
                MMA_F16(Sf[2 * n4 + 1], qf[d], kb1[1], kb1[3]);
            }
        }

        const int r0 = q0 + wrow + grp;
        if (kt >= 2 * qt) {
#pragma unroll
            for (int nb = 0; nb < 8; nb++) {
#pragma unroll
                for (int j = 0; j < 2; j++) {
                    int key = kt * 64 + nb * 8 + qq + j;
                    if (key > r0)     Sf[nb][j]     = -1e30f;
                    if (key > r0 + 8) Sf[nb][2 + j] = -1e30f;
                }
            }
        }

        float mx0 = -1e30f, mx1 = -1e30f;
#pragma unroll
        for (int nb = 0; nb < 8; nb++) {
            mx0 = fmaxf(mx0, fmaxf(Sf[nb][0], Sf[nb][1]));
            mx1 = fmaxf(mx1, fmaxf(Sf[nb][2], Sf[nb][3]));
        }
        mx0 = fmaxf(mx0, __shfl_xor_sync(0xffffffff, mx0, 1));
        mx0 = fmaxf(mx0, __shfl_xor_sync(0xffffffff, mx0, 2));
        mx1 = fmaxf(mx1, __shfl_xor_sync(0xffffffff, mx1, 1));
        mx1 = fmaxf(mx1, __shfl_xor_sync(0xffffffff, mx1, 2));
        float mn0 = fmaxf(m0, mx0), mn1 = fmaxf(m1, mx1);
        float a0 = __expf(m0 - mn0), a1 = __expf(m1 - mn1);
        float s0 = 0.f, s1 = 0.f;
#pragma unroll
        for (int nb = 0; nb < 8; nb++) {
            Sf[nb][0] = __expf(Sf[nb][0] - mn0); s0 += Sf[nb][0];
            Sf[nb][1] = __expf(Sf[nb][1] - mn0); s0 += Sf[nb][1];
            Sf[nb][2] = __expf(Sf[nb][2] - mn1); s1 += Sf[nb][2];
            Sf[nb][3] = __expf(Sf[nb][3] - mn1); s1 += Sf[nb][3];
        }
        s0 += __shfl_xor_sync(0xffffffff, s0, 1);
        s0 += __shfl_xor_sync(0xffffffff, s0, 2);
        s1 += __shfl_xor_sync(0xffffffff, s1, 1);
        s1 += __shfl_xor_sync(0xffffffff, s1, 2);
        l0 = l0 * a0 + s0;  l1 = l1 * a1 + s1;
        m0 = mn0;           m1 = mn1;
#pragma unroll
        for (int nb = 0; nb < 16; nb++) {
            Of[nb][0] *= a0; Of[nb][1] *= a0;
            Of[nb][2] *= a1; Of[nb][3] *= a1;
        }

        // O += P V  (P 1-digit fp16, V 2-digit)
        const uint32_t vb = kvb + 2 * FTILE * 2;
#pragma unroll
        for (int j = 0; j < 4; j++) {
            uint32_t ph[4];
            ph[0] = pack_h2(Sf[2 * j][0],     Sf[2 * j][1]);
            ph[1] = pack_h2(Sf[2 * j][2],     Sf[2 * j][3]);
            ph[2] = pack_h2(Sf[2 * j + 1][0], Sf[2 * j + 1][1]);
            ph[3] = pack_h2(Sf[2 * j + 1][2], Sf[2 * j + 1][3]);
#pragma unroll
            for (int nb2 = 0; nb2 < 8; nb2++) {
                uint32_t addr = vb + ((j * 16 + ldr) * FSTR + nb2 * 16 + ldc) * 2;
                uint32_t vh[4], vl[4];
                LDMX4T(vh, addr);
                LDMX4T(vl, addr + FTILE * 2);
                MMA_F16(Of[2 * nb2],     ph, vh[0], vh[1]);
                MMA_F16(Of[2 * nb2 + 1], ph, vh[2], vh[3]);
                MMA_F16(Of[2 * nb2],     ph, vl[0], vl[1]);
                MMA_F16(Of[2 * nb2 + 1], ph, vl[2], vl[3]);
            }
        }

        __syncthreads();
        if (kt + 2 <= ktmax) load_kv(kt + 2, kt & 1);
    }

    const int b = bh >> 4, h = bh & 15;
    const float inv0 = 1.0f / l0, inv1 = 1.0f / l1;
    const size_t row0 = (size_t)(b * SSQ + q0 + wrow + grp) * DDIM + (h << 7);
    const size_t row1 = row0 + (size_t)8 * DDIM;
#pragma unroll
    for (int nb = 0; nb < 16; nb++) {
        *(uint32_t*)(oh + row0 + nb * 8 + qq) =
            pack_h2(Of[nb][0] * inv0, Of[nb][1] * inv0);
        *(uint32_t*)(oh + row1 + nb * 8 + qq) =
            pack_h2(Of[nb][2] * inv1, Of[nb][3] * inv1);
    }
}

// ---------------------------------------------------------------------------
// Launch
// ---------------------------------------------------------------------------
extern "C" void kernel_launch(void* const* d_in, const int* in_sizes, int n_in,
                              void* d_out, int out_size)
{
    const float* x     = (const float*)d_in[0];
    const float* wqkv  = (const float*)d_in[1];
    const float* wout  = (const float*)d_in[2];
    const float* fcos  = (const float*)d_in[3];
    const float* fsin  = (const float*)d_in[4];
    float* out = (float*)d_out;

    __half *xh, *w1hi, *w1lo, *w2hi, *w2lo, *ah;
    __half *qh, *khi, *klo, *vhi, *vlo;
    cudaGetSymbolAddress((void**)&xh,   g_xh);
    cudaGetSymbolAddress((void**)&w1hi, g_w1hi);
    cudaGetSymbolAddress((void**)&w1lo, g_w1lo);
    cudaGetSymbolAddress((void**)&w2hi, g_w2hi);
    cudaGetSymbolAddress((void**)&w2lo, g_w2lo);
    cudaGetSymbolAddress((void**)&ah,   g_ah);
    cudaGetSymbolAddress((void**)&qh,   g_qh);
    cudaGetSymbolAddress((void**)&khi,  g_khi);
    cudaGetSymbolAddress((void**)&klo,  g_klo);
    cudaGetSymbolAddress((void**)&vhi,  g_vhi);
    cudaGetSymbolAddress((void**)&vlo,  g_vlo);

    cudaFuncSetAttribute(mma_gemm_t<0>,
                         cudaFuncAttributeMaxDynamicSharedMemorySize, GEMM_SMEM);
    cudaFuncSetAttribute(mma_gemm_t<1>,
                         cudaFuncAttributeMaxDynamicSharedMemorySize, GEMM_SMEM);
    cudaFuncSetAttribute(flash_mma,
                         cudaFuncAttributeMaxDynamicSharedMemorySize, FLASH_SMEM);

    const int nx  = M1 * DDIM / 4;
    const int nw1 = N1 * DDIM / 4;
    const int nw2 = DDIM * DDIM / 4;

    // operand conversion / splits
    cvt_h  <<<(nx  + 255) / 256, 256>>>(x, xh, nx);
    split_h<<<(nw1 + 255) / 256, 256>>>(wqkv, w1hi, w1lo, nw1);
    split_h<<<(nw2 + 255) / 256, 256>>>(wout, w2hi, w2lo, nw2);

    // 1) QKV projection with fused RoPE + relayout epilogue
    mma_gemm_t<1><<<dim3(N1 / 128, M1 / 128), 256, GEMM_SMEM>>>(
        xh, w1hi, w1lo, nullptr, N1, DDIM, fcos, fsin);

    // 2) Flash attention -> writes g_ah (fp16, GEMM2 A operand)
    flash_mma<<<dim3(SSQ / 128, FB), 256, FLASH_SMEM>>>(
        qh, khi, klo, vhi, vlo, ah);

    // 3) Output projection
    mma_gemm_t<0><<<dim3(DDIM / 128, M1 / 128), 256, GEMM_SMEM>>>(
        ah, w2hi, w2lo, out, DDIM, DDIM, nullptr, nullptr);
}

// round 13
// speedup vs baseline: 5.0298x; 1.5017x over previous
#include <cuda_runtime.h>
#include <cuda_fp16.h>
#include <cstdint>

// Problem constants
#define BB 2
#define SSQ 2048
#define DDIM 2048
#define HH 16
#define M1 (BB * SSQ)      // 4096
#define N1 (3 * DDIM)      // 6144
#define FB (BB * HH)       // 32 (b,h) pairs

// ---------------------------------------------------------------------------
// Scratch (__device__ globals). fp16 operands.
// GEMM1: A=x 1-digit, B=w1 1-digit.  GEMM2: A=O 1-digit, B=w2 2-digit.
// Flash: Q,K,V all 1-digit.
// ---------------------------------------------------------------------------
__device__ __half g_xh  [(size_t)M1 * DDIM];
__device__ __half g_w1h [(size_t)N1 * DDIM];
__device__ __half g_w2hi[(size_t)DDIM * DDIM];
__device__ __half g_w2lo[(size_t)DDIM * DDIM];
__device__ __half g_ah  [(size_t)M1 * DDIM];          // flash out (GEMM2 A)
// flash operands, layout [bh][s][128]
__device__ __half g_qh[(size_t)FB * SSQ * 128];
__device__ __half g_kh[(size_t)FB * SSQ * 128];
__device__ __half g_vh[(size_t)FB * SSQ * 128];

__device__ __forceinline__ uint32_t smem_u32(const void* p) {
    uint32_t a;
    asm("{ .reg .u64 t; cvta.to.shared.u64 t, %1; cvt.u32.u64 %0, t; }"
        : "=r"(a) : "l"(p));
    return a;
}

#define LDMX4(R, A) \
    asm volatile("ldmatrix.sync.aligned.m8n8.x4.shared.b16 {%0,%1,%2,%3}, [%4];" \
        : "=r"((R)[0]), "=r"((R)[1]), "=r"((R)[2]), "=r"((R)[3]) : "r"(A))
#define LDMX4T(R, A) \
    asm volatile("ldmatrix.sync.aligned.m8n8.x4.trans.shared.b16 {%0,%1,%2,%3}, [%4];" \
        : "=r"((R)[0]), "=r"((R)[1]), "=r"((R)[2]), "=r"((R)[3]) : "r"(A))

#define MMA_F16(ac, a, b0v, b1v) \
    asm volatile("mma.sync.aligned.m16n8k16.row.col.f32.f16.f16.f32 " \
        "{%0,%1,%2,%3},{%4,%5,%6,%7},{%8,%9},{%0,%1,%2,%3};" \
        : "+f"((ac)[0]), "+f"((ac)[1]), "+f"((ac)[2]), "+f"((ac)[3]) \
        : "r"((a)[0]), "r"((a)[1]), "r"((a)[2]), "r"((a)[3]), \
          "r"(b0v), "r"(b1v))

#define CP_ASYNC16(s, g) \
    asm volatile("cp.async.cg.shared.global [%0], [%1], 16;" :: "r"(s), "l"(g))
#define CP_COMMIT() asm volatile("cp.async.commit_group;" ::: "memory")
#define CP_WAIT1()  asm volatile("cp.async.wait_group 1;" ::: "memory")
#define CP_WAIT0()  asm volatile("cp.async.wait_group 0;" ::: "memory")

__device__ __forceinline__ uint32_t pack_h2(float x, float y) {
    __half2 h = __floats2half2_rn(x, y);
    return *reinterpret_cast<uint32_t*>(&h);
}
__device__ __forceinline__ void split_h2(float x, float y,
                                         uint32_t& hi, uint32_t& lo) {
    __half2 h = __floats2half2_rn(x, y);
    hi = *reinterpret_cast<uint32_t*>(&h);
    __half2 l = __floats2half2_rn(x - __low2float(h), y - __high2float(h));
    lo = *reinterpret_cast<uint32_t*>(&l);
}

// ---------------------------------------------------------------------------
// fp32 -> fp16 convert and fp32 -> fp16 hi/lo split
// ---------------------------------------------------------------------------
__global__ __launch_bounds__(256) void cvt_h(
    const float* __restrict__ src, __half* __restrict__ dst, int n4)
{
    int i = blockIdx.x * blockDim.x + threadIdx.x;
    if (i >= n4) return;
    float4 v = ((const float4*)src)[i];
    ((uint32_t*)dst)[i * 2 + 0] = pack_h2(v.x, v.y);
    ((uint32_t*)dst)[i * 2 + 1] = pack_h2(v.z, v.w);
}

__global__ __launch_bounds__(256) void split_h(
    const float* __restrict__ src, __half* __restrict__ hi,
    __half* __restrict__ lo, int n4)
{
    int i = blockIdx.x * blockDim.x + threadIdx.x;
    if (i >= n4) return;
    float4 v = ((const float4*)src)[i];
    uint32_t h0, l0, h1, l1;
    split_h2(v.x, v.y, h0, l0);
    split_h2(v.z, v.w, h1, l1);
    ((uint32_t*)hi)[i * 2 + 0] = h0;
    ((uint32_t*)hi)[i * 2 + 1] = h1;
    ((uint32_t*)lo)[i * 2 + 0] = l0;
    ((uint32_t*)lo)[i * 2 + 1] = l1;
}

// ---------------------------------------------------------------------------
// mma.sync fp16 GEMM:  C[M,N] = A[M,K] * W[N,K]^T.
// BDIG = digits of B operand (1 or 2); A is always 1-digit.
// CTA 128x128, 256 threads (8 warps, warp tile 64x32), k-chunk 32,
// double-buffered cp.async, 2 CTAs/SM.
//  MODE 0: plain fp32 store;  MODE 1: fused RoPE + relayout (q/k/v 1-digit)
// ---------------------------------------------------------------------------
#define KC 32
#define AST 40                           // padded row stride (fp16, 80 B)
#define TILE_B 10240                     // one 128x32 tile (bytes)

template <int MODE, int BDIG>
__global__ __launch_bounds__(256, 2) void mma_gemm_t(
    const __half* __restrict__ A, const __half* __restrict__ Bhi,
    const __half* __restrict__ Blo, float* __restrict__ C, int Ntot, int K,
    const float* __restrict__ fc, const float* __restrict__ fs)
{
    constexpr int NT = 1 + BDIG;                 // tiles per stage
    constexpr uint32_t STAGE = NT * TILE_B;
    extern __shared__ __half smh[];
    const uint32_t sbase = smem_u32(smh);
    const int t = threadIdx.x;
    const int lane = t & 31, warp = t >> 5;
    const int bm = blockIdx.y << 7;
    const int bn = blockIdx.x << 7;
    const int wm = (warp >> 2) << 6;   // 0 / 64
    const int wn = (warp & 3) << 5;    // 0,32,64,96

    const int lr = t >> 1;
    const int lc0 = (t & 1) << 1;

    const __half* gsrc[3] = {
        A   + (size_t)(bm + lr) * K,
        Bhi + (size_t)(bn + lr) * K,
        BDIG == 2 ? Blo + (size_t)(bn + lr) * K : Bhi };

    auto load_stage = [&](int kc, int buf) {
        uint32_t sb = sbase + buf * STAGE;
#pragma unroll
        for (int tile = 0; tile < NT; tile++) {
#pragma unroll
            for (int i = 0; i < 2; i++) {
                int c = lc0 + i;
                uint32_t sa = sb + tile * TILE_B + (lr * AST + c * 8) * 2;
                const void* ga = gsrc[tile] + kc * KC + c * 8;
                CP_ASYNC16(sa, ga);
            }
        }
        CP_COMMIT();
    };

    float acc[4][4][4] = {};
    const int NIT = K / KC;

    load_stage(0, 0);

    const int ldrow = lane & 15;
    const int ldcol = (lane >> 4) << 3;

    for (int it = 0; it < NIT; it++) {
        if (it + 1 < NIT) { load_stage(it + 1, (it + 1) & 1); CP_WAIT1(); }
        else              { CP_WAIT0(); }
        __syncthreads();

        const uint32_t sb = sbase + (it & 1) * STAGE;
#pragma unroll
        for (int kh = 0; kh < 2; kh++) {
            uint32_t aF[4][4], bH[4][2], bL[4][2];
            const int colb = (kh * 16 + ldcol) * 2;
#pragma unroll
            for (int mt = 0; mt < 4; mt++) {
                uint32_t ra = sb + (wm + mt * 16 + ldrow) * (AST * 2) + colb;
                LDMX4(aF[mt], ra);
            }
#pragma unroll
            for (int n2 = 0; n2 < 2; n2++) {
                uint32_t rb = sb + TILE_B +
                              (wn + n2 * 16 + ldrow) * (AST * 2) + colb;
                uint32_t r[4];
                LDMX4(r, rb);
                bH[n2 * 2 + 0][0] = r[0]; bH[n2 * 2 + 0][1] = r[2];
                bH[n2 * 2 + 1][0] = r[1]; bH[n2 * 2 + 1][1] = r[3];
                if (BDIG == 2) {
                    LDMX4(r, rb + TILE_B);
                    bL[n2 * 2 + 0][0] = r[0]; bL[n2 * 2 + 0][1] = r[2];
                    bL[n2 * 2 + 1][0] = r[1]; bL[n2 * 2 + 1][1] = r[3];
                }
            }
#pragma unroll
            for (int mt = 0; mt < 4; mt++) {
#pragma unroll
                for (int nt = 0; nt < 4; nt++) {
                    MMA_F16(acc[mt][nt], aF[mt], bH[nt][0], bH[nt][1]);
                    if (BDIG == 2)
                        MMA_F16(acc[mt][nt], aF[mt], bL[nt][0], bL[nt][1]);
                }
            }
        }
        __syncthreads();
    }

    const int grp = lane >> 2, qq = (lane & 3) << 1;

    if (MODE == 0) {
#pragma unroll
        for (int mt = 0; mt < 4; mt++) {
#pragma unroll
            for (int nt = 0; nt < 4; nt++) {
                float* p = C + (size_t)(bm + wm + mt * 16 + grp) * Ntot
                             + bn + wn + nt * 8 + qq;
                *(float2*)p = make_float2(acc[mt][nt][0], acc[mt][nt][1]);
                *(float2*)(p + (size_t)8 * Ntot) =
                    make_float2(acc[mt][nt][2], acc[mt][nt][3]);
            }
        }
    } else {
        // fused RoPE + relayout; CTA-uniform region (q/k/v)
        const int region = bn >> 11;            // 0=q, 1=k, 2=v
        const float scale = 0.08838834764831845f; // 1/sqrt(128)
#pragma unroll
        for (int mt = 0; mt < 4; mt++) {
            const int r0 = bm + wm + mt * 16 + grp;
            const int b  = r0 >> 11;
            const int s0 = r0 & (SSQ - 1);
            const int s1 = s0 + 8;
#pragma unroll
            for (int nt = 0; nt < 4; nt++) {
                const int c  = bn + wn + nt * 8 + qq;
                const int cr = c & (DDIM - 1);
                const int h  = cr >> 7;
                const int ch = cr & 127;
                const int i  = ch >> 1;
                const size_t ob = ((size_t)(b * HH + h) * SSQ);
                const size_t o0 = (ob + s0) * 128 + ch;
                const size_t o1 = (ob + s1) * 128 + ch;
                float x0 = acc[mt][nt][0], y0 = acc[mt][nt][1];
                float x1 = acc[mt][nt][2], y1 = acc[mt][nt][3];
                if (region == 2) {
                    *(uint32_t*)(g_vh + o0) = pack_h2(x0, y0);
                    *(uint32_t*)(g_vh + o1) = pack_h2(x1, y1);
                } else {
                    float c0 = fc[(s0 << 6) + i], sn0 = fs[(s0 << 6) + i];
                    float c1 = fc[(s1 << 6) + i], sn1 = fs[(s1 << 6) + i];
                    float rx0 = x0 * c0 - y0 * sn0, ry0 = x0 * sn0 + y0 * c0;
                    float rx1 = x1 * c1 - y1 * sn1, ry1 = x1 * sn1 + y1 * c1;
                    if (region == 0) {
                        *(uint32_t*)(g_qh + o0) = pack_h2(rx0 * scale, ry0 * scale);
                        *(uint32_t*)(g_qh + o1) = pack_h2(rx1 * scale, ry1 * scale);
                    } else {
                        *(uint32_t*)(g_kh + o0) = pack_h2(rx0, ry0);
                        *(uint32_t*)(g_kh + o1) = pack_h2(rx1, ry1);
                    }
                }
            }
        }
    }
}

// ---------------------------------------------------------------------------
// Flash attention on fp16 mma.sync: Q, K, V, P all 1-digit.
// QK: 2 MMAs per (d,n4).  PV: 2 MMAs per (j,nb2).
// ---------------------------------------------------------------------------
#define FSTR 136
#define FTILE (64 * FSTR)
#define QTILE (128 * FSTR)
#define FLASH_SMEM ((QTILE + 4 * FTILE) * 2)   // 104448 bytes

__global__ __launch_bounds__(256, 1) void flash_mma(
    const __half* __restrict__ qh_, const __half* __restrict__ kh_,
    const __half* __restrict__ vh_, __half* __restrict__ oh)
{
    extern __shared__ __half fsm[];
    const uint32_t sb = smem_u32(fsm);
    const int t = threadIdx.x;
    const int lane = t & 31, warp = t >> 5;
    const int qt = (int)gridDim.x - 1 - (int)blockIdx.x;
    const int bh = blockIdx.y;
    const int q0 = qt << 7;
    const size_t bhbase = (size_t)bh * SSQ * 128;

    const int ldr = lane & 15;
    const int ldc = (lane >> 4) << 3;
    const int grp = lane >> 2;
    const int qq  = (lane & 3) << 1;

    // stage Q
    {
        int r = t >> 1;
        int e0 = (t & 1) << 6;
        const __half* src = qh_ + bhbase + (size_t)(q0 + r) * 128 + e0;
        uint32_t s0 = sb + (r * FSTR + e0) * 2;
#pragma unroll
        for (int c = 0; c < 8; c++)
            CP_ASYNC16(s0 + c * 16, src + c * 8);
        CP_COMMIT();
    }

    auto load_kv = [&](int kt, int buf) {
        int r = t >> 2;
        int e0 = (t & 3) << 5;
        size_t g0 = bhbase + (size_t)(kt * 64 + r) * 128 + e0;
        const __half* srcs[2] = { kh_ + g0, vh_ + g0 };
        uint32_t s0 = sb + (QTILE + buf * 2 * FTILE + r * FSTR + e0) * 2;
#pragma unroll
        for (int tile = 0; tile < 2; tile++)
#pragma unroll
            for (int c = 0; c < 4; c++)
                CP_ASYNC16(s0 + tile * FTILE * 2 + c * 16, srcs[tile] + c * 8);
        CP_COMMIT();
    };

    CP_WAIT0();
    __syncthreads();
    uint32_t qf[8][4];
    const int wrow = warp << 4;
#pragma unroll
    for (int d = 0; d < 8; d++) {
        uint32_t a = sb + ((wrow + ldr) * FSTR + d * 16 + ldc) * 2;
        LDMX4(qf[d], a);
    }

    const int ktmax = 2 * qt + 1;
    load_kv(0, 0);
    load_kv(1, 1);

    float Of[16][4] = {};
    float m0 = -1e30f, m1 = -1e30f, l0 = 0.f, l1 = 0.f;

    for (int kt = 0; kt <= ktmax; kt++) {
        if (kt == ktmax) { CP_WAIT0(); } else { CP_WAIT1(); }
        __syncthreads();

        const uint32_t kvb = sb + (QTILE + (kt & 1) * 2 * FTILE) * 2;

        float Sf[8][4] = {};
#pragma unroll
        for (int d = 0; d < 8; d++) {
#pragma unroll
            for (int n4 = 0; n4 < 4; n4++) {
                uint32_t addr = kvb + ((n4 * 16 + ldr) * FSTR + d * 16 + ldc) * 2;
                uint32_t kb[4];
                LDMX4(kb, addr);
                MMA_F16(Sf[2 * n4],     qf[d], kb[0], kb[2]);
                MMA_F16(Sf[2 * n4 + 1], qf[d], kb[1], kb[3]);
            }
        }

        const int r0 = q0 + wrow + grp;
        if (kt >= 2 * qt) {
#pragma unroll
            for (int nb = 0; nb < 8; nb++) {
#pragma unroll
                for (int j = 0; j < 2; j++) {
                    int key = kt * 64 + nb * 8 + qq + j;
                    if (key > r0)     Sf[nb][j]     = -1e30f;
                    if (key > r0 + 8) Sf[nb][2 + j] = -1e30f;
                }
            }
        }

        float mx0 = -1e30f, mx1 = -1e30f;
#pragma unroll
        for (int nb = 0; nb < 8; nb++) {
            mx0 = fmaxf(mx0, fmaxf(Sf[nb][0], Sf[nb][1]));
            mx1 = fmaxf(mx1, fmaxf(Sf[nb][2], Sf[nb][3]));
        }
        mx0 = fmaxf(mx0, __shfl_xor_sync(0xffffffff, mx0, 1));
        mx0 = fmaxf(mx0, __shfl_xor_sync(0xffffffff, mx0, 2));
        mx1 = fmaxf(mx1, __shfl_xor_sync(0xffffffff, mx1, 1));
        mx1 = fmaxf(mx1, __shfl_xor_sync(0xffffffff, mx1, 2));
        float mn0 = fmaxf(m0, mx0), mn1 = fmaxf(m1, mx1);
        float a0 = __expf(m0 - mn0), a1 = __expf(m1 - mn1);
        float s0 = 0.f, s1 = 0.f;
#pragma unroll
        for (int nb = 0; nb < 8; nb++) {
            Sf[nb][0] = __expf(Sf[nb][0] - mn0); s0 += Sf[nb][0];
            Sf[nb][1] = __expf(Sf[nb][1] - mn0); s0 += Sf[nb][1];
            Sf[nb][2] = __expf(Sf[nb][2] - mn1); s1 += Sf[nb][2];
            Sf[nb][3] = __expf(Sf[nb][3] - mn1); s1 += Sf[nb][3];
        }
        s0 += __shfl_xor_sync(0xffffffff, s0, 1);
        s0 += __shfl_xor_sync(0xffffffff, s0, 2);
        s1 += __shfl_xor_sync(0xffffffff, s1, 1);
        s1 += __shfl_xor_sync(0xffffffff, s1, 2);
        l0 = l0 * a0 + s0;  l1 = l1 * a1 + s1;
        m0 = mn0;           m1 = mn1;
#pragma unroll
        for (int nb = 0; nb < 16; nb++) {
            Of[nb][0] *= a0; Of[nb][1] *= a0;
            Of[nb][2] *= a1; Of[nb][3] *= a1;
        }

        // O += P V
        const uint32_t vb = kvb + FTILE * 2;
#pragma unroll
        for (int j = 0; j < 4; j++) {
            uint32_t ph[4];
            ph[0] = pack_h2(Sf[2 * j][0],     Sf[2 * j][1]);
            ph[1] = pack_h2(Sf[2 * j][2],     Sf[2 * j][3]);
            ph[2] = pack_h2(Sf[2 * j + 1][0], Sf[2 * j + 1][1]);
            ph[3] = pack_h2(Sf[2 * j + 1][2], Sf[2 * j + 1][3]);
#pragma unroll
            for (int nb2 = 0; nb2 < 8; nb2++) {
                uint32_t addr = vb + ((j * 16 + ldr) * FSTR + nb2 * 16 + ldc) * 2;
                uint32_t vf[4];
                LDMX4T(vf, addr);
                MMA_F16(Of[2 * nb2],     ph, vf[0], vf[1]);
                MMA_F16(Of[2 * nb2 + 1], ph, vf[2], vf[3]);
            }
        }

        __syncthreads();
        if (kt + 2 <= ktmax) load_kv(kt + 2, kt & 1);
    }

    const int b = bh >> 4, h = bh & 15;
    const float inv0 = 1.0f / l0, inv1 = 1.0f / l1;
    const size_t row0 = (size_t)(b * SSQ + q0 + wrow + grp) * DDIM + (h << 7);
    const size_t row1 = row0 + (size_t)8 * DDIM;
#pragma unroll
    for (int nb = 0; nb < 16; nb++) {
        *(uint32_t*)(oh + row0 + nb * 8 + qq) =
            pack_h2(Of[nb][0] * inv0, Of[nb][1] * inv0);
        *(uint32_t*)(oh + row1 + nb * 8 + qq) =
            pack_h2(Of[nb][2] * inv1, Of[nb][3] * inv1);
    }
}

// ---------------------------------------------------------------------------
// Launch
// ---------------------------------------------------------------------------
extern "C" void kernel_launch(void* const* d_in, const int* in_sizes, int n_in,
                              void* d_out, int out_size)
{
    const float* x     = (const float*)d_in[0];
    const float* wqkv  = (const float*)d_in[1];
    const float* wout  = (const float*)d_in[2];
    const float* fcos  = (const float*)d_in[3];
    const float* fsin  = (const float*)d_in[4];
    float* out = (float*)d_out;

    __half *xh, *w1h, *w2hi, *w2lo, *ah, *qh, *kh, *vh;
    cudaGetSymbolAddress((void**)&xh,   g_xh);
    cudaGetSymbolAddress((void**)&w1h,  g_w1h);
    cudaGetSymbolAddress((void**)&w2hi, g_w2hi);
    cudaGetSymbolAddress((void**)&w2lo, g_w2lo);
    cudaGetSymbolAddress((void**)&ah,   g_ah);
    cudaGetSymbolAddress((void**)&qh,   g_qh);
    cudaGetSymbolAddress((void**)&kh,   g_kh);
    cudaGetSymbolAddress((void**)&vh,   g_vh);

    const int smem_g1 = 2 * 2 * TILE_B;   // BDIG=1: 40960
    const int smem_g2 = 2 * 3 * TILE_B;   // BDIG=2: 61440
    cudaFuncSetAttribute(mma_gemm_t<1, 1>,
                         cudaFuncAttributeMaxDynamicSharedMemorySize, smem_g1);
    cudaFuncSetAttribute(mma_gemm_t<0, 2>,
                         cudaFuncAttributeMaxDynamicSharedMemorySize, smem_g2);
    cudaFuncSetAttribute(flash_mma,
                         cudaFuncAttributeMaxDynamicSharedMemorySize, FLASH_SMEM);

    const int nx  = M1 * DDIM / 4;
    const int nw1 = N1 * DDIM / 4;
    const int nw2 = DDIM * DDIM / 4;

    // operand conversion / splits
    cvt_h  <<<(nx  + 255) / 256, 256>>>(x, xh, nx);
    cvt_h  <<<(nw1 + 255) / 256, 256>>>(wqkv, w1h, nw1);
    split_h<<<(nw2 + 255) / 256, 256>>>(wout, w2hi, w2lo, nw2);

    // 1) QKV projection (single-MMA fp16) with fused RoPE + relayout
    mma_gemm_t<1, 1><<<dim3(N1 / 128, M1 / 128), 256, smem_g1>>>(
        xh, w1h, nullptr, nullptr, N1, DDIM, fcos, fsin);

    // 2) Flash attention (1-digit Q/K/V) -> g_ah
    flash_mma<<<dim3(SSQ / 128, FB), 256, FLASH_SMEM>>>(qh, kh, vh, ah);

    // 3) Output projection (A 1-digit, w2 2-digit for final precision)
    mma_gemm_t<0, 2><<<dim3(DDIM / 128, M1 / 128), 256, smem_g2>>>(
        ah, w2hi, w2lo, out, DDIM, DDIM, nullptr, nullptr);
}

// round 14
// speedup vs baseline: 5.7271x; 1.1386x over previous
#include <cuda_runtime.h>
#include <cuda_fp16.h>
#include <cstdint>

// Problem constants
#define BB 2
#define SSQ 2048
#define DDIM 2048
#define HH 16
#define M1 (BB * SSQ)      // 4096
#define N1 (3 * DDIM)      // 6144
#define FB (BB * HH)       // 32 (b,h) pairs

// ---------------------------------------------------------------------------
// Scratch (__device__ globals). fp16 operands, all 1-digit.
// ---------------------------------------------------------------------------
__device__ __half g_xh [(size_t)M1 * DDIM];
__device__ __half g_w1h[(size_t)N1 * DDIM];
__device__ __half g_w2h[(size_t)DDIM * DDIM];
__device__ __half g_ah [(size_t)M1 * DDIM];           // flash out (GEMM2 A)
// flash operands, layout [bh][s][128]
__device__ __half g_qh[(size_t)FB * SSQ * 128];
__device__ __half g_kh[(size_t)FB * SSQ * 128];
__device__ __half g_vh[(size_t)FB * SSQ * 128];

__device__ __forceinline__ uint32_t smem_u32(const void* p) {
    uint32_t a;
    asm("{ .reg .u64 t; cvta.to.shared.u64 t, %1; cvt.u32.u64 %0, t; }"
        : "=r"(a) : "l"(p));
    return a;
}

#define LDMX4(R, A) \
    asm volatile("ldmatrix.sync.aligned.m8n8.x4.shared.b16 {%0,%1,%2,%3}, [%4];" \
        : "=r"((R)[0]), "=r"((R)[1]), "=r"((R)[2]), "=r"((R)[3]) : "r"(A))
#define LDMX4T(R, A) \
    asm volatile("ldmatrix.sync.aligned.m8n8.x4.trans.shared.b16 {%0,%1,%2,%3}, [%4];" \
        : "=r"((R)[0]), "=r"((R)[1]), "=r"((R)[2]), "=r"((R)[3]) : "r"(A))

#define MMA_F16(ac, a, b0v, b1v) \
    asm volatile("mma.sync.aligned.m16n8k16.row.col.f32.f16.f16.f32 " \
        "{%0,%1,%2,%3},{%4,%5,%6,%7},{%8,%9},{%0,%1,%2,%3};" \
        : "+f"((ac)[0]), "+f"((ac)[1]), "+f"((ac)[2]), "+f"((ac)[3]) \
        : "r"((a)[0]), "r"((a)[1]), "r"((a)[2]), "r"((a)[3]), \
          "r"(b0v), "r"(b1v))

#define CP_ASYNC16(s, g) \
    asm volatile("cp.async.cg.shared.global [%0], [%1], 16;" :: "r"(s), "l"(g))
#define CP_COMMIT() asm volatile("cp.async.commit_group;" ::: "memory")
#define CP_WAIT1()  asm volatile("cp.async.wait_group 1;" ::: "memory")
#define CP_WAIT0()  asm volatile("cp.async.wait_group 0;" ::: "memory")

__device__ __forceinline__ uint32_t pack_h2(float x, float y) {
    __half2 h = __floats2half2_rn(x, y);
    return *reinterpret_cast<uint32_t*>(&h);
}

// ---------------------------------------------------------------------------
// fp32 -> fp16 convert
// ---------------------------------------------------------------------------
__global__ __launch_bounds__(256) void cvt_h(
    const float* __restrict__ src, __half* __restrict__ dst, int n4)
{
    int i = blockIdx.x * blockDim.x + threadIdx.x;
    if (i >= n4) return;
    float4 v = ((const float4*)src)[i];
    ((uint32_t*)dst)[i * 2 + 0] = pack_h2(v.x, v.y);
    ((uint32_t*)dst)[i * 2 + 1] = pack_h2(v.z, v.w);
}

// ---------------------------------------------------------------------------
// mma.sync fp16 GEMM:  C[M,N] = A[M,K] * W[N,K]^T, both operands 1-digit.
// CTA 128x128, 256 threads (8 warps, warp tile 64x32), k-chunk 32,
// double-buffered cp.async, 2 CTAs/SM.
//  MODE 0: plain fp32 store;  MODE 1: fused RoPE + relayout (q/k/v)
// ---------------------------------------------------------------------------
#define KC 32
#define AST 40                           // padded row stride (fp16, 80 B)
#define TILE_B 10240                     // one 128x32 tile (bytes)
#define STAGE (2 * TILE_B)               // A, B
#define GEMM_SMEM (2 * STAGE)            // 40960

template <int MODE>
__global__ __launch_bounds__(256, 2) void mma_gemm_t(
    const __half* __restrict__ A, const __half* __restrict__ B,
    float* __restrict__ C, int Ntot, int K,
    const float* __restrict__ fc, const float* __restrict__ fs)
{
    extern __shared__ __half smh[];
    const uint32_t sbase = smem_u32(smh);
    const int t = threadIdx.x;
    const int lane = t & 31, warp = t >> 5;
    const int bm = blockIdx.y << 7;
    const int bn = blockIdx.x << 7;
    const int wm = (warp >> 2) << 6;   // 0 / 64
    const int wn = (warp & 3) << 5;    // 0,32,64,96

    const int lr = t >> 1;
    const int lc0 = (t & 1) << 1;

    const __half* gsrc[2] = {
        A + (size_t)(bm + lr) * K,
        B + (size_t)(bn + lr) * K };

    auto load_stage = [&](int kc, int buf) {
        uint32_t sb = sbase + buf * STAGE;
#pragma unroll
        for (int tile = 0; tile < 2; tile++) {
#pragma unroll
            for (int i = 0; i < 2; i++) {
                int c = lc0 + i;
                uint32_t sa = sb + tile * TILE_B + (lr * AST + c * 8) * 2;
                const void* ga = gsrc[tile] + kc * KC + c * 8;
                CP_ASYNC16(sa, ga);
            }
        }
        CP_COMMIT();
    };

    float acc[4][4][4] = {};
    const int NIT = K / KC;

    load_stage(0, 0);

    const int ldrow = lane & 15;
    const int ldcol = (lane >> 4) << 3;

    for (int it = 0; it < NIT; it++) {
        if (it + 1 < NIT) { load_stage(it + 1, (it + 1) & 1); CP_WAIT1(); }
        else              { CP_WAIT0(); }
        __syncthreads();

        const uint32_t sb = sbase + (it & 1) * STAGE;
#pragma unroll
        for (int kh = 0; kh < 2; kh++) {
            uint32_t aF[4][4], bF[4][2];
            const int colb = (kh * 16 + ldcol) * 2;
#pragma unroll
            for (int mt = 0; mt < 4; mt++) {
                uint32_t ra = sb + (wm + mt * 16 + ldrow) * (AST * 2) + colb;
                LDMX4(aF[mt], ra);
            }
#pragma unroll
            for (int n2 = 0; n2 < 2; n2++) {
                uint32_t rb = sb + TILE_B +
                              (wn + n2 * 16 + ldrow) * (AST * 2) + colb;
                uint32_t r[4];
                LDMX4(r, rb);
                bF[n2 * 2 + 0][0] = r[0]; bF[n2 * 2 + 0][1] = r[2];
                bF[n2 * 2 + 1][0] = r[1]; bF[n2 * 2 + 1][1] = r[3];
            }
#pragma unroll
            for (int mt = 0; mt < 4; mt++) {
#pragma unroll
                for (int nt = 0; nt < 4; nt++)
                    MMA_F16(acc[mt][nt], aF[mt], bF[nt][0], bF[nt][1]);
            }
        }
        __syncthreads();
    }

    const int grp = lane >> 2, qq = (lane & 3) << 1;

    if (MODE == 0) {
#pragma unroll
        for (int mt = 0; mt < 4; mt++) {
#pragma unroll
            for (int nt = 0; nt < 4; nt++) {
                float* p = C + (size_t)(bm + wm + mt * 16 + grp) * Ntot
                             + bn + wn + nt * 8 + qq;
                *(float2*)p = make_float2(acc[mt][nt][0], acc[mt][nt][1]);
                *(float2*)(p + (size_t)8 * Ntot) =
                    make_float2(acc[mt][nt][2], acc[mt][nt][3]);
            }
        }
    } else {
        // fused RoPE + relayout; CTA-uniform region (q/k/v)
        const int region = bn >> 11;            // 0=q, 1=k, 2=v
        const float scale = 0.08838834764831845f; // 1/sqrt(128)
#pragma unroll
        for (int mt = 0; mt < 4; mt++) {
            const int r0 = bm + wm + mt * 16 + grp;
            const int b  = r0 >> 11;
            const int s0 = r0 & (SSQ - 1);
            const int s1 = s0 + 8;
#pragma unroll
            for (int nt = 0; nt < 4; nt++) {
                const int c  = bn + wn + nt * 8 + qq;
                const int cr = c & (DDIM - 1);
                const int h  = cr >> 7;
                const int ch = cr & 127;
                const int i  = ch >> 1;
                const size_t ob = ((size_t)(b * HH + h) * SSQ);
                const size_t o0 = (ob + s0) * 128 + ch;
                const size_t o1 = (ob + s1) * 128 + ch;
                float x0 = acc[mt][nt][0], y0 = acc[mt][nt][1];
                float x1 = acc[mt][nt][2], y1 = acc[mt][nt][3];
                if (region == 2) {
                    *(uint32_t*)(g_vh + o0) = pack_h2(x0, y0);
                    *(uint32_t*)(g_vh + o1) = pack_h2(x1, y1);
                } else {
                    float c0 = fc[(s0 << 6) + i], sn0 = fs[(s0 << 6) + i];
                    float c1 = fc[(s1 << 6) + i], sn1 = fs[(s1 << 6) + i];
                    float rx0 = x0 * c0 - y0 * sn0, ry0 = x0 * sn0 + y0 * c0;
                    float rx1 = x1 * c1 - y1 * sn1, ry1 = x1 * sn1 + y1 * c1;
                    if (region == 0) {
                        *(uint32_t*)(g_qh + o0) = pack_h2(rx0 * scale, ry0 * scale);
                        *(uint32_t*)(g_qh + o1) = pack_h2(rx1 * scale, ry1 * scale);
                    } else {
                        *(uint32_t*)(g_kh + o0) = pack_h2(rx0, ry0);
                        *(uint32_t*)(g_kh + o1) = pack_h2(rx1, ry1);
                    }
                }
            }
        }
    }
}

// ---------------------------------------------------------------------------
// Flash attention on fp16 mma.sync: Q, K, V, P all 1-digit.
// ---------------------------------------------------------------------------
#define FSTR 136
#define FTILE (64 * FSTR)
#define QTILE (128 * FSTR)
#define FLASH_SMEM ((QTILE + 4 * FTILE) * 2)   // 104448 bytes

__global__ __launch_bounds__(256, 1) void flash_mma(
    const __half* __restrict__ qh_, const __half* __restrict__ kh_,
    const __half* __restrict__ vh_, __half* __restrict__ oh)
{
    extern __shared__ __half fsm[];
    const uint32_t sb = smem_u32(fsm);
    const int t = threadIdx.x;
    const int lane = t & 31, warp = t >> 5;
    const int qt = (int)gridDim.x - 1 - (int)blockIdx.x;
    const int bh = blockIdx.y;
    const int q0 = qt << 7;
    const size_t bhbase = (size_t)bh * SSQ * 128;

    const int ldr = lane & 15;
    const int ldc = (lane >> 4) << 3;
    const int grp = lane >> 2;
    const int qq  = (lane & 3) << 1;

    // stage Q
    {
        int r = t >> 1;
        int e0 = (t & 1) << 6;
        const __half* src = qh_ + bhbase + (size_t)(q0 + r) * 128 + e0;
        uint32_t s0 = sb + (r * FSTR + e0) * 2;
#pragma unroll
        for (int c = 0; c < 8; c++)
            CP_ASYNC16(s0 + c * 16, src + c * 8);
        CP_COMMIT();
    }

    auto load_kv = [&](int kt, int buf) {
        int r = t >> 2;
        int e0 = (t & 3) << 5;
        size_t g0 = bhbase + (size_t)(kt * 64 + r) * 128 + e0;
        const __half* srcs[2] = { kh_ + g0, vh_ + g0 };
        uint32_t s0 = sb + (QTILE + buf * 2 * FTILE + r * FSTR + e0) * 2;
#pragma unroll
        for (int tile = 0; tile < 2; tile++)
#pragma unroll
            for (int c = 0; c < 4; c++)
                CP_ASYNC16(s0 + tile * FTILE * 2 + c * 16, srcs[tile] + c * 8);
        CP_COMMIT();
    };

    CP_WAIT0();
    __syncthreads();
    uint32_t qf[8][4];
    const int wrow = warp << 4;
#pragma unroll
    for (int d = 0; d < 8; d++) {
        uint32_t a = sb + ((wrow + ldr) * FSTR + d * 16 + ldc) * 2;
        LDMX4(qf[d], a);
    }

    const int ktmax = 2 * qt + 1;
    load_kv(0, 0);
    load_kv(1, 1);

    float Of[16][4] = {};
    float m0 = -1e30f, m1 = -1e30f, l0 = 0.f, l1 = 0.f;

    for (int kt = 0; kt <= ktmax; kt++) {
        if (kt == ktmax) { CP_WAIT0(); } else { CP_WAIT1(); }
        __syncthreads();

        const uint32_t kvb = sb + (QTILE + (kt & 1) * 2 * FTILE) * 2;

        float Sf[8][4] = {};
#pragma unroll
        for (int d = 0; d < 8; d++) {
#pragma unroll
            for (int n4 = 0; n4 < 4; n4++) {
                uint32_t addr = kvb + ((n4 * 16 + ldr) * FSTR + d * 16 + ldc) * 2;
                uint32_t kb[4];
                LDMX4(kb, addr);
                MMA_F16(Sf[2 * n4],     qf[d], kb[0], kb[2]);
                MMA_F16(Sf[2 * n4 + 1], qf[d], kb[1], kb[3]);
            }
        }

        const int r0 = q0 + wrow + grp;
        if (kt >= 2 * qt) {
#pragma unroll
            for (int nb = 0; nb < 8; nb++) {
#pragma unroll
                for (int j = 0; j < 2; j++) {
                    int key = kt * 64 + nb * 8 + qq + j;
                    if (key > r0)     Sf[nb][j]     = -1e30f;
                    if (key > r0 + 8) Sf[nb][2 + j] = -1e30f;
                }
            }
        }

        float mx0 = -1e30f, mx1 = -1e30f;
#pragma unroll
        for (int nb = 0; nb < 8; nb++) {
            mx0 = fmaxf(mx0, fmaxf(Sf[nb][0], Sf[nb][1]));
            mx1 = fmaxf(mx1, fmaxf(Sf[nb][2], Sf[nb][3]));
        }
        mx0 = fmaxf(mx0, __shfl_xor_sync(0xffffffff, mx0, 1));
        mx0 = fmaxf(mx0, __shfl_xor_sync(0xffffffff, mx0, 2));
        mx1 = fmaxf(mx1, __shfl_xor_sync(0xffffffff, mx1, 1));
        mx1 = fmaxf(mx1, __shfl_xor_sync(0xffffffff, mx1, 2));
        float mn0 = fmaxf(m0, mx0), mn1 = fmaxf(m1, mx1);
        float a0 = __expf(m0 - mn0), a1 = __expf(m1 - mn1);
        float s0 = 0.f, s1 = 0.f;
#pragma unroll
        for (int nb = 0; nb < 8; nb++) {
            Sf[nb][0] = __expf(Sf[nb][0] - mn0); s0 += Sf[nb][0];
            Sf[nb][1] = __expf(Sf[nb][1] - mn0); s0 += Sf[nb][1];
            Sf[nb][2] = __expf(Sf[nb][2] - mn1); s1 += Sf[nb][2];
            Sf[nb][3] = __expf(Sf[nb][3] - mn1); s1 += Sf[nb][3];
        }
        s0 += __shfl_xor_sync(0xffffffff, s0, 1);
        s0 += __shfl_xor_sync(0xffffffff, s0, 2);
        s1 += __shfl_xor_sync(0xffffffff, s1, 1);
        s1 += __shfl_xor_sync(0xffffffff, s1, 2);
        l0 = l0 * a0 + s0;  l1 = l1 * a1 + s1;
        m0 = mn0;           m1 = mn1;
#pragma unroll
        for (int nb = 0; nb < 16; nb++) {
            Of[nb][0] *= a0; Of[nb][1] *= a0;
            Of[nb][2] *= a1; Of[nb][3] *= a1;
        }

        // O += P V
        const uint32_t vb = kvb + FTILE * 2;
#pragma unroll
        for (int j = 0; j < 4; j++) {
            uint32_t ph[4];
            ph[0] = pack_h2(Sf[2 * j][0],     Sf[2 * j][1]);
            ph[1] = pack_h2(Sf[2 * j][2],     Sf[2 * j][3]);
            ph[2] = pack_h2(Sf[2 * j + 1][0], Sf[2 * j + 1][1]);
            ph[3] = pack_h2(Sf[2 * j + 1][2], Sf[2 * j + 1][3]);
#pragma unroll
            for (int nb2 = 0; nb2 < 8; nb2++) {
                uint32_t addr = vb + ((j * 16 + ldr) * FSTR + nb2 * 16 + ldc) * 2;
                uint32_t vf[4];
                LDMX4T(vf, addr);
                MMA_F16(Of[2 * nb2],     ph, vf[0], vf[1]);
                MMA_F16(Of[2 * nb2 + 1], ph, vf[2], vf[3]);
            }
        }

        __syncthreads();
        if (kt + 2 <= ktmax) load_kv(kt + 2, kt & 1);
    }

    const int b = bh >> 4, h = bh & 15;
    const float inv0 = 1.0f / l0, inv1 = 1.0f / l1;
    const size_t row0 = (size_t)(b * SSQ + q0 + wrow + grp) * DDIM + (h << 7);
    const size_t row1 = row0 + (size_t)8 * DDIM;
#pragma unroll
    for (int nb = 0; nb < 16; nb++) {
        *(uint32_t*)(oh + row0 + nb * 8 + qq) =
            pack_h2(Of[nb][0] * inv0, Of[nb][1] * inv0);
        *(uint32_t*)(oh + row1 + nb * 8 + qq) =
            pack_h2(Of[nb][2] * inv1, Of[nb][3] * inv1);
    }
}

// ---------------------------------------------------------------------------
// Launch
// ---------------------------------------------------------------------------
extern "C" void kernel_launch(void* const* d_in, const int* in_sizes, int n_in,
                              void* d_out, int out_size)
{
    const float* x     = (const float*)d_in[0];
    const float* wqkv  = (const float*)d_in[1];
    const float* wout  = (const float*)d_in[2];
    const float* fcos  = (const float*)d_in[3];
    const float* fsin  = (const float*)d_in[4];
    float* out = (float*)d_out;

    __half *xh, *w1h, *w2h, *ah, *qh, *kh, *vh;
    cudaGetSymbolAddress((void**)&xh,  g_xh);
    cudaGetSymbolAddress((void**)&w1h, g_w1h);
    cudaGetSymbolAddress((void**)&w2h, g_w2h);
    cudaGetSymbolAddress((void**)&ah,  g_ah);
    cudaGetSymbolAddress((void**)&qh,  g_qh);
    cudaGetSymbolAddress((void**)&kh,  g_kh);
    cudaGetSymbolAddress((void**)&vh,  g_vh);

    cudaFuncSetAttribute(mma_gemm_t<0>,
                         cudaFuncAttributeMaxDynamicSharedMemorySize, GEMM_SMEM);
    cudaFuncSetAttribute(mma_gemm_t<1>,
                         cudaFuncAttributeMaxDynamicSharedMemorySize, GEMM_SMEM);
    cudaFuncSetAttribute(flash_mma,
                         cudaFuncAttributeMaxDynamicSharedMemorySize, FLASH_SMEM);

    const int nx  = M1 * DDIM / 4;
    const int nw1 = N1 * DDIM / 4;
    const int nw2 = DDIM * DDIM / 4;

    // operand conversion
    cvt_h<<<(nx  + 255) / 256, 256>>>(x, xh, nx);
    cvt_h<<<(nw1 + 255) / 256, 256>>>(wqkv, w1h, nw1);
    cvt_h<<<(nw2 + 255) / 256, 256>>>(wout, w2h, nw2);

    // 1) QKV projection (single-MMA fp16) with fused RoPE + relayout
    mma_gemm_t<1><<<dim3(N1 / 128, M1 / 128), 256, GEMM_SMEM>>>(
        xh, w1h, nullptr, N1, DDIM, fcos, fsin);

    // 2) Flash attention (1-digit Q/K/V) -> g_ah
    flash_mma<<<dim3(SSQ / 128, FB), 256, FLASH_SMEM>>>(qh, kh, vh, ah);

    // 3) Output projection (1-digit both operands)
    mma_gemm_t<0><<<dim3(DDIM / 128, M1 / 128), 256, GEMM_SMEM>>>(
        ah, w2h, out, DDIM, DDIM, nullptr, nullptr);
}